// round 14
// baseline (speedup 1.0000x reference)
#include <cuda_runtime.h>
#include <cstdint>

#define HDIM 128
#define TSEQ 512
#define BATCH 128
#define GB 4
#define RSTRIDE 132
#define WSTRIDE 132
#define ASTRIDE 132     // activation row stride; dims 64..127 live at float-offset 68
#define GSTRIDE 9       // gate-buffer row stride -> conflict-free scalar access
#define TBLK 64         // t-block size in tiled attention kernel

typedef unsigned long long u64;

__device__ float g_h2[(size_t)TSEQ * BATCH * HDIM];   // [t][b][h]
__device__ float g_dold[TSEQ * BATCH];
__device__ float g_dh[TSEQ * BATCH];
__device__ float g_mx[TSEQ];
__device__ float g_inv[TSEQ];

__device__ __forceinline__ float sigm(float x) {
    return __fdividef(1.f, 1.f + __expf(-x));
}
__device__ __forceinline__ float tanh_fast(float x) {
    x = fminf(fmaxf(x, -15.f), 15.f);
    float e = __expf(2.f * x);
    return __fdividef(e - 1.f, e + 1.f);
}
__device__ __forceinline__ u64 ffma2(u64 a, u64 b, u64 c) {
    u64 d;
    asm("fma.rn.f32x2 %0, %1, %2, %3;" : "=l"(d) : "l"(a), "l"(b), "l"(c));
    return d;
}
__device__ __forceinline__ float sum2(u64 v) {
    float lo, hi;
    asm("mov.b64 {%0, %1}, %2;" : "=f"(lo), "=f"(hi) : "l"(v));
    return lo + hi;
}
__device__ __forceinline__ void st_cluster_f32(float* p, int rank, float v) {
    uint32_t la = (uint32_t)__cvta_generic_to_shared(p);
    uint32_t ra;
    asm volatile("mapa.shared::cluster.u32 %0, %1, %2;" : "=r"(ra) : "r"(la), "r"(rank));
    asm volatile("st.shared::cluster.f32 [%0], %1;" :: "r"(ra), "f"(v) : "memory");
}
__device__ __forceinline__ void mbar_init(uint32_t a, uint32_t cnt) {
    asm volatile("mbarrier.init.shared.b64 [%0], %1;" :: "r"(a), "r"(cnt) : "memory");
}
__device__ __forceinline__ void mbar_arrive_rank(uint32_t local_addr, uint32_t rank) {
    asm volatile(
        "{\n\t.reg .b32 ra;\n\t"
        "mapa.shared::cluster.u32 ra, %0, %1;\n\t"
        "mbarrier.arrive.release.cluster.shared::cluster.b64 _, [ra];\n\t}"
        :: "r"(local_addr), "r"(rank) : "memory");
}
__device__ __forceinline__ void mbar_wait(uint32_t addr, uint32_t parity) {
    asm volatile(
        "{\n\t.reg .pred P;\n"
        "WL_%=:\n\t"
        "mbarrier.try_wait.parity.acquire.cluster.shared::cta.b64 P, [%0], %1, 0x989680;\n\t"
        "@P bra WD_%=;\n\t"
        "bra WL_%=;\n"
        "WD_%=:\n\t}"
        :: "r"(addr), "r"(parity) : "memory");
}
__device__ __forceinline__ void cluster_sync_() {
    asm volatile("barrier.cluster.arrive.aligned;" ::: "memory");
    asm volatile("barrier.cluster.wait.aligned;" ::: "memory");
}

// ---------------------------------------------------------------------------
// Phase 1 (R13, best measured 1.432-1.437 ms): layer-split warp specialization.
// ---------------------------------------------------------------------------
__global__ void __launch_bounds__(256, 1) __cluster_dims__(4, 1, 1)
lstm_seq_kernel(const float* __restrict__ x,
                const float* __restrict__ Wih1, const float* __restrict__ Whh1,
                const float* __restrict__ bih1, const float* __restrict__ bhh1,
                const float* __restrict__ Wih2, const float* __restrict__ Whh2,
                const float* __restrict__ bih2, const float* __restrict__ bhh2)
{
    extern __shared__ float sW2[];   // [256][WSTRIDE] rows 0-127 Wih2, 128-255 Whh2; kh-gap cols

    __shared__ __align__(16) float h1bc[2][GB * ASTRIDE];
    __shared__ __align__(16) float c1bc[2][GB * ASTRIDE];
    __shared__ __align__(16) float h2bc[2][GB * ASTRIDE];
    __shared__ float g1buf[128 * GSTRIDE];
    __shared__ float g2buf[128 * GSTRIDE];
    __shared__ float bias1s[128], bias2s[128], wih1s[128];
    __shared__ __align__(8) u64 mbar[2];

    const int tid  = threadIdx.x;
    const int rank = blockIdx.x & 3;
    const int bg0  = (blockIdx.x >> 2) * GB;
    const int lt   = tid & 127;

    const int cu   = lt & 31, cb = lt >> 5;
    const int slot = rank * 32 + cu;
    const int pos  = slot + (slot >= 64 ? 4 : 0);

    u64 w1[64];
    if (tid < 128) {
        const int gr = (lt >> 5) * 128 + rank * 32 + (lt & 31);
        const float* src = Whh1 + (size_t)gr * 128;
        #pragma unroll
        for (int k = 0; k < 32; k++) {
            ulonglong2 v = ((const ulonglong2*)src)[k];
            w1[2 * k] = v.x; w1[2 * k + 1] = v.y;
        }
    }

    for (int idx = tid; idx < 256 * 32; idx += 256) {
        int j = idx >> 5, k4 = idx & 31;
        int jr = j & 127;
        int gr = (jr >> 5) * 128 + rank * 32 + (jr & 31);
        const float* src = ((j >> 7) ? Whh2 : Wih2) + (size_t)gr * 128 + k4 * 4;
        int dstc = (k4 < 16) ? (k4 * 4) : (k4 * 4 + 4);
        *(float4*)(sW2 + j * WSTRIDE + dstc) = *(const float4*)src;
    }
    if (tid < 128) {
        int gr = (tid >> 5) * 128 + rank * 32 + (tid & 31);
        bias1s[tid] = bih1[gr] + bhh1[gr];
        bias2s[tid] = bih2[gr] + bhh2[gr];
        wih1s[tid]  = Wih1[gr];
    }
    for (int idx = tid; idx < 2 * GB * ASTRIDE; idx += 256) {
        ((float*)h1bc)[idx] = 0.f;
        ((float*)c1bc)[idx] = 0.f;
        ((float*)h2bc)[idx] = 0.f;
    }
    const uint32_t mb1a = (uint32_t)__cvta_generic_to_shared(&mbar[0]);
    const uint32_t mb2a = (uint32_t)__cvta_generic_to_shared(&mbar[1]);
    if (tid == 0) { mbar_init(mb1a, 4); mbar_init(mb2a, 4); }
    __syncthreads();
    cluster_sync_();

    if (tid < 128) {
        // ============================ GROUP A ============================
        float c1s = 0.f;
        const float* xp = x + (size_t)(bg0 + cb) * TSEQ;
        for (int i = 0; i < TSEQ; i++) {
            const int p  = i & 1;
            const int pn = p ^ 1;
            if (i > 0) mbar_wait(mb1a, (uint32_t)((i - 1) & 1));

            {
                const ulonglong2* hA = (const ulonglong2*)(&h1bc[p][0 * ASTRIDE]);
                const ulonglong2* hB = (const ulonglong2*)(&h1bc[p][1 * ASTRIDE]);
                const ulonglong2* hC = (const ulonglong2*)(&h1bc[p][2 * ASTRIDE]);
                const ulonglong2* hD = (const ulonglong2*)(&h1bc[p][3 * ASTRIDE]);
                u64 a0 = 0, a1 = 0, a2 = 0, a3 = 0;
                #pragma unroll
                for (int k = 0; k < 32; k++) {
                    int ki = k + (k >= 16 ? 1 : 0);
                    ulonglong2 v0 = hA[ki], v1 = hB[ki], v2 = hC[ki], v3 = hD[ki];
                    u64 wa = w1[2 * k], wb = w1[2 * k + 1];
                    a0 = ffma2(wa, v0.x, a0); a0 = ffma2(wb, v0.y, a0);
                    a1 = ffma2(wa, v1.x, a1); a1 = ffma2(wb, v1.y, a1);
                    a2 = ffma2(wa, v2.x, a2); a2 = ffma2(wb, v2.y, a2);
                    a3 = ffma2(wa, v3.x, a3); a3 = ffma2(wb, v3.y, a3);
                }
                g1buf[lt * GSTRIDE + 0] = sum2(a0);
                g1buf[lt * GSTRIDE + 1] = sum2(a1);
                g1buf[lt * GSTRIDE + 2] = sum2(a2);
                g1buf[lt * GSTRIDE + 3] = sum2(a3);
            }
            asm volatile("bar.sync 1, 128;" ::: "memory");
            if (i > 0) mbar_wait(mb2a, (uint32_t)((i - 1) & 1));

            {
                float xv = __ldg(xp + i);
                float gi = g1buf[(cu)      * GSTRIDE + cb] + fmaf(wih1s[cu],      xv, bias1s[cu]);
                float gf = g1buf[(32 + cu) * GSTRIDE + cb] + fmaf(wih1s[32 + cu], xv, bias1s[32 + cu]);
                float gg = g1buf[(64 + cu) * GSTRIDE + cb] + fmaf(wih1s[64 + cu], xv, bias1s[64 + cu]);
                float go = g1buf[(96 + cu) * GSTRIDE + cb] + fmaf(wih1s[96 + cu], xv, bias1s[96 + cu]);
                c1s = sigm(gf) * c1s + sigm(gi) * tanh_fast(gg);
                float h1n = sigm(go) * tanh_fast(c1s);
                #pragma unroll
                for (int r = 0; r < 4; r++) {
                    st_cluster_f32(&h1bc[pn][cb * ASTRIDE + pos], r, h1n);
                    st_cluster_f32(&c1bc[pn][cb * ASTRIDE + pos], r, c1s);
                }
            }
            asm volatile("bar.sync 1, 128;" ::: "memory");
            if (lt == 0) {
                #pragma unroll
                for (int r = 0; r < 4; r++) mbar_arrive_rank(mb1a, r);
            }
        }
    } else {
        // ============================ GROUP B ============================
        const int u  = lt >> 1;
        const int kh = lt & 1;
        const int r0 = 2 * u, r1 = 2 * u + 1;
        float c2s = 0.f;
        float* gh2p = g_h2 + (size_t)(bg0 + cb) * HDIM + slot;

        if (lt == 0) {
            #pragma unroll
            for (int r = 0; r < 4; r++) mbar_arrive_rank(mb2a, r);
        }
        for (int i = 1; i <= TSEQ; i++) {
            const int p  = i & 1;
            const int pn = p ^ 1;
            const uint32_t wpar = (uint32_t)((i - 1) & 1);
            mbar_wait(mb1a, wpar);
            mbar_wait(mb2a, wpar);

            {
                const ulonglong2* wi0 = (const ulonglong2*)(sW2 + r0 * WSTRIDE + kh * 68);
                const ulonglong2* wi1 = (const ulonglong2*)(sW2 + r1 * WSTRIDE + kh * 68);
                const ulonglong2* wh0 = (const ulonglong2*)(sW2 + (128 + r0) * WSTRIDE + kh * 68);
                const ulonglong2* wh1 = (const ulonglong2*)(sW2 + (128 + r1) * WSTRIDE + kh * 68);
                const ulonglong2* cA = (const ulonglong2*)(&c1bc[p][0 * ASTRIDE + kh * 68]);
                const ulonglong2* cB = (const ulonglong2*)(&c1bc[p][1 * ASTRIDE + kh * 68]);
                const ulonglong2* cC = (const ulonglong2*)(&c1bc[p][2 * ASTRIDE + kh * 68]);
                const ulonglong2* cD = (const ulonglong2*)(&c1bc[p][3 * ASTRIDE + kh * 68]);
                const ulonglong2* hA = (const ulonglong2*)(&h2bc[p][0 * ASTRIDE + kh * 68]);
                const ulonglong2* hB = (const ulonglong2*)(&h2bc[p][1 * ASTRIDE + kh * 68]);
                const ulonglong2* hC = (const ulonglong2*)(&h2bc[p][2 * ASTRIDE + kh * 68]);
                const ulonglong2* hD = (const ulonglong2*)(&h2bc[p][3 * ASTRIDE + kh * 68]);
                u64 p00 = 0, p01 = 0, p02 = 0, p03 = 0;
                u64 p10 = 0, p11 = 0, p12 = 0, p13 = 0;
                #pragma unroll
                for (int k = 0; k < 16; k++) {
                    ulonglong2 wiA = wi0[k], wiB = wi1[k];
                    ulonglong2 whA = wh0[k], whB = wh1[k];
                    ulonglong2 v0 = cA[k], v1 = cB[k], v2 = cC[k], v3 = cD[k];
                    ulonglong2 u0 = hA[k], u1 = hB[k], u2 = hC[k], u3 = hD[k];
                    p00 = ffma2(wiA.x, v0.x, p00); p00 = ffma2(wiA.y, v0.y, p00);
                    p00 = ffma2(whA.x, u0.x, p00); p00 = ffma2(whA.y, u0.y, p00);
                    p01 = ffma2(wiA.x, v1.x, p01); p01 = ffma2(wiA.y, v1.y, p01);
                    p01 = ffma2(whA.x, u1.x, p01); p01 = ffma2(whA.y, u1.y, p01);
                    p02 = ffma2(wiA.x, v2.x, p02); p02 = ffma2(wiA.y, v2.y, p02);
                    p02 = ffma2(whA.x, u2.x, p02); p02 = ffma2(whA.y, u2.y, p02);
                    p03 = ffma2(wiA.x, v3.x, p03); p03 = ffma2(wiA.y, v3.y, p03);
                    p03 = ffma2(whA.x, u3.x, p03); p03 = ffma2(whA.y, u3.y, p03);
                    p10 = ffma2(wiB.x, v0.x, p10); p10 = ffma2(wiB.y, v0.y, p10);
                    p10 = ffma2(whB.x, u0.x, p10); p10 = ffma2(whB.y, u0.y, p10);
                    p11 = ffma2(wiB.x, v1.x, p11); p11 = ffma2(wiB.y, v1.y, p11);
                    p11 = ffma2(whB.x, u1.x, p11); p11 = ffma2(whB.y, u1.y, p11);
                    p12 = ffma2(wiB.x, v2.x, p12); p12 = ffma2(wiB.y, v2.y, p12);
                    p12 = ffma2(whB.x, u2.x, p12); p12 = ffma2(whB.y, u2.y, p12);
                    p13 = ffma2(wiB.x, v3.x, p13); p13 = ffma2(wiB.y, v3.y, p13);
                    p13 = ffma2(whB.x, u3.x, p13); p13 = ffma2(whB.y, u3.y, p13);
                }
                float s00 = sum2(p00), s01 = sum2(p01), s02 = sum2(p02), s03 = sum2(p03);
                float s10 = sum2(p10), s11 = sum2(p11), s12 = sum2(p12), s13 = sum2(p13);
                s00 += __shfl_xor_sync(0xffffffffu, s00, 1);
                s01 += __shfl_xor_sync(0xffffffffu, s01, 1);
                s02 += __shfl_xor_sync(0xffffffffu, s02, 1);
                s03 += __shfl_xor_sync(0xffffffffu, s03, 1);
                s10 += __shfl_xor_sync(0xffffffffu, s10, 1);
                s11 += __shfl_xor_sync(0xffffffffu, s11, 1);
                s12 += __shfl_xor_sync(0xffffffffu, s12, 1);
                s13 += __shfl_xor_sync(0xffffffffu, s13, 1);
                if (kh == 0) {
                    float* q0 = &g2buf[r0 * GSTRIDE];
                    float* q1 = &g2buf[r1 * GSTRIDE];
                    q0[0] = s00; q0[1] = s01; q0[2] = s02; q0[3] = s03;
                    q1[0] = s10; q1[1] = s11; q1[2] = s12; q1[3] = s13;
                }
            }
            asm volatile("bar.sync 2, 128;" ::: "memory");

            {
                float gi = g2buf[(cu)      * GSTRIDE + cb] + bias2s[cu];
                float gf = g2buf[(32 + cu) * GSTRIDE + cb] + bias2s[32 + cu];
                float gg = g2buf[(64 + cu) * GSTRIDE + cb] + bias2s[64 + cu];
                float go = g2buf[(96 + cu) * GSTRIDE + cb] + bias2s[96 + cu];
                c2s = sigm(gf) * c2s + sigm(gi) * tanh_fast(gg);
                float h2n = sigm(go) * tanh_fast(c2s);
                if (i < TSEQ) {
                    #pragma unroll
                    for (int r = 0; r < 4; r++)
                        st_cluster_f32(&h2bc[pn][cb * ASTRIDE + pos], r, h2n);
                }
                gh2p[(size_t)(i - 1) * (BATCH * HDIM)] = h2n;
            }
            asm volatile("bar.sync 2, 128;" ::: "memory");
            if (lt == 0 && i < TSEQ) {
                #pragma unroll
                for (int r = 0; r < 4; r++) mbar_arrive_rank(mb2a, r);
            }
        }
    }
}

// ---------------------------------------------------------------------------
__global__ void dots_kernel(const float* __restrict__ w_t)
{
    int gid  = blockIdx.x * blockDim.x + threadIdx.x;
    int gw   = gid >> 5;
    int lane = gid & 31;
    if (gw >= TSEQ * BATCH) return;
    float4 h = *(const float4*)(g_h2 + (size_t)gw * HDIM + lane * 4);
    float4 a = *(const float4*)(w_t + lane * 4);
    float4 o = *(const float4*)(w_t + HDIM + lane * 4);
    float dh   = h.x * a.x + h.y * a.y + h.z * a.z + h.w * a.w;
    float dold = h.x * o.x + h.y * o.y + h.z * o.z + h.w * o.w;
    #pragma unroll
    for (int off = 16; off; off >>= 1) {
        dh   += __shfl_down_sync(0xffffffffu, dh, off);
        dold += __shfl_down_sync(0xffffffffu, dold, off);
    }
    if (lane == 0) { g_dh[gw] = dh; g_dold[gw] = dold; }
}

// ---------------------------------------------------------------------------
// Phase 2a': per-t global softmax stats over the valid (slot,batch) set.
// valid slot s <-> h2 time idx = t-33+s; slot valid iff idx >= -1
// (idx == -1 is the zero buffer row: score = dh only).
// ---------------------------------------------------------------------------
__global__ void __launch_bounds__(256, 1)
softmax_stats_kernel()
{
    __shared__ float sRed[256];
    const int t   = blockIdx.x;
    const int tid = threadIdx.x;

    float lmax = -1e30f;
    for (int n = tid; n < 33 * 128; n += 256) {
        int s = n >> 7, b = n & 127;
        int idx = t - 33 + s;
        if (idx >= -1) {
            float sc = g_dh[t * BATCH + b] + (idx >= 0 ? g_dold[idx * BATCH + b] : 0.f);
            lmax = fmaxf(lmax, sc);
        }
    }
    sRed[tid] = lmax; __syncthreads();
    for (int off = 128; off; off >>= 1) {
        if (tid < off) sRed[tid] = fmaxf(sRed[tid], sRed[tid + off]);
        __syncthreads();
    }
    float mx = sRed[0];
    __syncthreads();
    float lsum = 0.f;
    for (int n = tid; n < 33 * 128; n += 256) {
        int s = n >> 7, b = n & 127;
        int idx = t - 33 + s;
        if (idx >= -1) {
            float sc = g_dh[t * BATCH + b] + (idx >= 0 ? g_dold[idx * BATCH + b] : 0.f);
            lsum += __expf(sc - mx);
        }
    }
    sRed[tid] = lsum; __syncthreads();
    for (int off = 128; off; off >>= 1) {
        if (tid < off) sRed[tid] += sRed[tid + off];
        __syncthreads();
    }
    if (tid == 0) {
        g_mx[t]  = mx;
        g_inv[t] = __fdividef(1.f, sRed[0]);
    }
}

// ---------------------------------------------------------------------------
// Phase 2b': tiled attention + FC. CTA = (t-block of TBLK=64, batch b).
// Loads the 97-row h2 strip for b ONCE into SMEM, precomputes all 64x33
// softmax weights from (dold, dh, mx, inv), gathers, then FC per t.
// ---------------------------------------------------------------------------
__global__ void __launch_bounds__(256, 1)
attn_fc_tile_kernel(const float* __restrict__ fcW, const float* __restrict__ fcb,
                    float* __restrict__ out)
{
    extern __shared__ float sm[];
    float* sFcT   = sm;                          // [128][132]  fcW^T [h][c]
    float* sH2    = sFcT + 128 * RSTRIDE;        // [97][132]   h2 strip (rows, r=time-(t0-33))
    float* sPre   = sH2 + 97 * RSTRIDE;          // [64][132]
    float* sW     = sPre + 64 * RSTRIDE;         // [64][33]
    float* sDoldv = sW + 64 * 33;                // [96]
    float* sDh    = sDoldv + 96;                 // [64]
    float* sMx    = sDh + 64;                    // [64]
    float* sInv   = sMx + 64;                    // [64]

    const int t0   = blockIdx.x * TBLK;
    const int b    = blockIdx.y;
    const int tid  = threadIdx.x;
    const int lane = tid & 31;
    const int warp = tid >> 5;

    // fcW^T
    for (int idx = tid; idx < 128 * 128; idx += 256) {
        int c = idx >> 7, h = idx & 127;
        sFcT[h * RSTRIDE + c] = fcW[idx];
    }
    // h2 strip: r = 0..96 -> time t0-33+r (zeros for time < 0)
    for (int idx = tid; idx < 97 * 128; idx += 256) {
        int r = idx >> 7, h = idx & 127;
        int time = t0 - 33 + r;
        sH2[r * RSTRIDE + h] = (time >= 0)
            ? g_h2[(size_t)time * (BATCH * HDIM) + (size_t)b * HDIM + h] : 0.f;
    }
    // scalar vectors
    for (int r = tid; r < 96; r += 256) {
        int time = t0 - 33 + r;
        sDoldv[r] = (time >= 0) ? g_dold[time * BATCH + b] : 0.f;
    }
    if (tid < TBLK) {
        sDh[tid]  = g_dh[(t0 + tid) * BATCH + b];
        sMx[tid]  = g_mx[t0 + tid];
        sInv[tid] = g_inv[t0 + tid];
    }
    __syncthreads();

    // softmax weights (0 for invalid slots idx < -1)
    for (int idx = tid; idx < TBLK * 33; idx += 256) {
        int tl = idx / 33, s = idx - tl * 33;
        int gidx = t0 + tl - 33 + s;
        float w = 0.f;
        if (gidx >= -1)
            w = __expf(sDoldv[tl + s] + sDh[tl] - sMx[tl]) * sInv[tl];
        sW[tl * 33 + s] = w;
    }
    __syncthreads();

    // attention gather + pre (warp per t, lane covers 4 h)
    for (int tl = warp; tl < TBLK; tl += 8) {
        float4 acc; acc.x = acc.y = acc.z = acc.w = 0.f;
        const float* wrow = &sW[tl * 33];
        #pragma unroll 1
        for (int s = 0; s < 33; s++) {
            float w = wrow[s];
            float4 v = *(const float4*)(&sH2[(tl + s) * RSTRIDE + lane * 4]);
            acc.x += w * v.x; acc.y += w * v.y; acc.z += w * v.z; acc.w += w * v.w;
        }
        float4 cur = *(const float4*)(&sH2[(tl + 33) * RSTRIDE + lane * 4]);
        float4 pre;
        pre.x = cur.x + acc.x; pre.y = cur.y + acc.y;
        pre.z = cur.z + acc.z; pre.w = cur.w + acc.w;
        *(float4*)(&sPre[tl * RSTRIDE + lane * 4]) = pre;
    }
    __syncthreads();

    // FC: thread = (lane -> c quad, warp (+8r) -> t)
    const int c0 = lane * 4;
    float4 bias = *(const float4*)(fcb + c0);
    for (int r8 = 0; r8 < 8; r8++) {
        int tl = warp + 8 * r8;
        float4 a0; a0.x = bias.x; a0.y = bias.y; a0.z = bias.z; a0.w = bias.w;
        const float4* pr = (const float4*)(&sPre[tl * RSTRIDE]);
        #pragma unroll
        for (int h4 = 0; h4 < 32; h4++) {
            float4 q = pr[h4];
            #pragma unroll
            for (int hh = 0; hh < 4; hh++) {
                float4 w = *(const float4*)(&sFcT[(h4 * 4 + hh) * RSTRIDE + c0]);
                float v = (&q.x)[hh];
                a0.x += v * w.x; a0.y += v * w.y; a0.z += v * w.z; a0.w += v * w.w;
            }
        }
        *(float4*)(out + (size_t)b * (TSEQ * 128) + (size_t)(t0 + tl) * 128 + c0) = a0;
    }
}

// ---------------------------------------------------------------------------
extern "C" void kernel_launch(void* const* d_in, const int* in_sizes, int n_in,
                              void* d_out, int out_size)
{
    const float* x    = (const float*)d_in[0];
    const float* Wih1 = (const float*)d_in[1];
    const float* Whh1 = (const float*)d_in[2];
    const float* bih1 = (const float*)d_in[3];
    const float* bhh1 = (const float*)d_in[4];
    const float* Wih2 = (const float*)d_in[5];
    const float* Whh2 = (const float*)d_in[6];
    const float* bih2 = (const float*)d_in[7];
    const float* bhh2 = (const float*)d_in[8];
    const float* w_t  = (const float*)d_in[9];
    const float* fcW  = (const float*)d_in[10];
    const float* fcb  = (const float*)d_in[11];
    float* out = (float*)d_out;

    const int smem1 = 256 * WSTRIDE * (int)sizeof(float);   // 135168
    const int smem2 = (128 * RSTRIDE + 97 * RSTRIDE + 64 * RSTRIDE
                       + 64 * 33 + 96 + 64 + 64 + 64) * (int)sizeof(float);  // ~162KB

    cudaFuncSetAttribute(lstm_seq_kernel, cudaFuncAttributeMaxDynamicSharedMemorySize, smem1);
    cudaFuncSetAttribute(attn_fc_tile_kernel, cudaFuncAttributeMaxDynamicSharedMemorySize, smem2);

    lstm_seq_kernel<<<128, 256, smem1>>>(x, Wih1, Whh1, bih1, bhh1,
                                         Wih2, Whh2, bih2, bhh2);
    dots_kernel<<<(TSEQ * BATCH * 32) / 256, 256>>>(w_t);
    softmax_stats_kernel<<<TSEQ, 256>>>();
    attn_fc_tile_kernel<<<dim3(TSEQ / TBLK, BATCH), 256, smem2>>>(fcW, fcb, out);
}

// round 15
// speedup vs baseline: 1.3534x; 1.3534x over previous
#include <cuda_runtime.h>
#include <cstdint>

#define HDIM 128
#define TSEQ 512
#define BATCH 128
#define GB 4
#define RSTRIDE 132
#define WSTRIDE 132
#define ASTRIDE 132     // activation row stride; dims 64..127 live at float-offset 68
#define GSTRIDE 9       // gate-buffer row stride -> conflict-free scalar access

typedef unsigned long long u64;

__device__ float g_h2[(size_t)TSEQ * BATCH * HDIM];   // [t][b][h]
__device__ float g_dold[TSEQ * BATCH];
__device__ float g_dh[TSEQ * BATCH];

__device__ __forceinline__ float sigm(float x) {
    return __fdividef(1.f, 1.f + __expf(-x));
}
__device__ __forceinline__ float tanh_fast(float x) {
    x = fminf(fmaxf(x, -15.f), 15.f);
    float e = __expf(2.f * x);
    return __fdividef(e - 1.f, e + 1.f);
}
__device__ __forceinline__ u64 ffma2(u64 a, u64 b, u64 c) {
    u64 d;
    asm("fma.rn.f32x2 %0, %1, %2, %3;" : "=l"(d) : "l"(a), "l"(b), "l"(c));
    return d;
}
__device__ __forceinline__ float sum2(u64 v) {
    float lo, hi;
    asm("mov.b64 {%0, %1}, %2;" : "=f"(lo), "=f"(hi) : "l"(v));
    return lo + hi;
}
__device__ __forceinline__ void st_cluster_f32(float* p, int rank, float v) {
    uint32_t la = (uint32_t)__cvta_generic_to_shared(p);
    uint32_t ra;
    asm volatile("mapa.shared::cluster.u32 %0, %1, %2;" : "=r"(ra) : "r"(la), "r"(rank));
    asm volatile("st.shared::cluster.f32 [%0], %1;" :: "r"(ra), "f"(v) : "memory");
}
__device__ __forceinline__ void mbar_init(uint32_t a, uint32_t cnt) {
    asm volatile("mbarrier.init.shared.b64 [%0], %1;" :: "r"(a), "r"(cnt) : "memory");
}
__device__ __forceinline__ void mbar_arrive_rank(uint32_t local_addr, uint32_t rank) {
    asm volatile(
        "{\n\t.reg .b32 ra;\n\t"
        "mapa.shared::cluster.u32 ra, %0, %1;\n\t"
        "mbarrier.arrive.release.cluster.shared::cluster.b64 _, [ra];\n\t}"
        :: "r"(local_addr), "r"(rank) : "memory");
}
__device__ __forceinline__ void mbar_wait(uint32_t addr, uint32_t parity) {
    asm volatile(
        "{\n\t.reg .pred P;\n"
        "WL_%=:\n\t"
        "mbarrier.try_wait.parity.acquire.cluster.shared::cta.b64 P, [%0], %1, 0x989680;\n\t"
        "@P bra WD_%=;\n\t"
        "bra WL_%=;\n"
        "WD_%=:\n\t}"
        :: "r"(addr), "r"(parity) : "memory");
}
__device__ __forceinline__ void cluster_sync_() {
    asm volatile("barrier.cluster.arrive.aligned;" ::: "memory");
    asm volatile("barrier.cluster.wait.aligned;" ::: "memory");
}

// ---------------------------------------------------------------------------
// Phase 1 (R13 + two critical-path trims):
//  - xs staged in SMEM again; xv loaded at ITERATION TOP (hidden under mv1)
//    instead of a naked L2 LDG inside cell1 (was ~234 cyc on the serial path).
//  - the 4 remote mbarrier arrives go from 1 elected thread (serial) to
//    4 threads (lt<4), one rank each; total arrive count per mbar unchanged.
// Layer-split warp specialization otherwise identical to R13.
// ---------------------------------------------------------------------------
__global__ void __launch_bounds__(256, 1) __cluster_dims__(4, 1, 1)
lstm_seq_kernel(const float* __restrict__ x,
                const float* __restrict__ Wih1, const float* __restrict__ Whh1,
                const float* __restrict__ bih1, const float* __restrict__ bhh1,
                const float* __restrict__ Wih2, const float* __restrict__ Whh2,
                const float* __restrict__ bih2, const float* __restrict__ bhh2)
{
    extern __shared__ float sW2[];   // [256][WSTRIDE] rows 0-127 Wih2, 128-255 Whh2; kh-gap cols

    __shared__ __align__(16) float h1bc[2][GB * ASTRIDE];
    __shared__ __align__(16) float c1bc[2][GB * ASTRIDE];
    __shared__ __align__(16) float h2bc[2][GB * ASTRIDE];
    __shared__ float xs[GB][TSEQ];
    __shared__ float g1buf[128 * GSTRIDE];
    __shared__ float g2buf[128 * GSTRIDE];
    __shared__ float bias1s[128], bias2s[128], wih1s[128];
    __shared__ __align__(8) u64 mbar[2];

    const int tid  = threadIdx.x;
    const int rank = blockIdx.x & 3;
    const int bg0  = (blockIdx.x >> 2) * GB;
    const int lt   = tid & 127;

    const int cu   = lt & 31, cb = lt >> 5;
    const int slot = rank * 32 + cu;
    const int pos  = slot + (slot >= 64 ? 4 : 0);

    u64 w1[64];
    if (tid < 128) {
        const int gr = (lt >> 5) * 128 + rank * 32 + (lt & 31);
        const float* src = Whh1 + (size_t)gr * 128;
        #pragma unroll
        for (int k = 0; k < 32; k++) {
            ulonglong2 v = ((const ulonglong2*)src)[k];
            w1[2 * k] = v.x; w1[2 * k + 1] = v.y;
        }
    }

    for (int idx = tid; idx < 256 * 32; idx += 256) {
        int j = idx >> 5, k4 = idx & 31;
        int jr = j & 127;
        int gr = (jr >> 5) * 128 + rank * 32 + (jr & 31);
        const float* src = ((j >> 7) ? Whh2 : Wih2) + (size_t)gr * 128 + k4 * 4;
        int dstc = (k4 < 16) ? (k4 * 4) : (k4 * 4 + 4);
        *(float4*)(sW2 + j * WSTRIDE + dstc) = *(const float4*)src;
    }
    if (tid < 128) {
        int gr = (tid >> 5) * 128 + rank * 32 + (tid & 31);
        bias1s[tid] = bih1[gr] + bhh1[gr];
        bias2s[tid] = bih2[gr] + bhh2[gr];
        wih1s[tid]  = Wih1[gr];
    }
    for (int idx = tid; idx < GB * TSEQ; idx += 256) {
        int b = idx >> 9, tt = idx & (TSEQ - 1);
        xs[b][tt] = x[(size_t)(bg0 + b) * TSEQ + tt];
    }
    for (int idx = tid; idx < 2 * GB * ASTRIDE; idx += 256) {
        ((float*)h1bc)[idx] = 0.f;
        ((float*)c1bc)[idx] = 0.f;
        ((float*)h2bc)[idx] = 0.f;
    }
    const uint32_t mb1a = (uint32_t)__cvta_generic_to_shared(&mbar[0]);
    const uint32_t mb2a = (uint32_t)__cvta_generic_to_shared(&mbar[1]);
    if (tid == 0) { mbar_init(mb1a, 4); mbar_init(mb2a, 4); }
    __syncthreads();
    cluster_sync_();

    if (tid < 128) {
        // ============================ GROUP A ============================
        float c1s = 0.f;
        for (int i = 0; i < TSEQ; i++) {
            const int p  = i & 1;
            const int pn = p ^ 1;
            if (i > 0) mbar_wait(mb1a, (uint32_t)((i - 1) & 1));

            float xv = xs[cb][i];   // hoisted: latency hidden under mv1

            // mv1: reg row (full K) . h1(i-1), 4 batches (gap act layout)
            {
                const ulonglong2* hA = (const ulonglong2*)(&h1bc[p][0 * ASTRIDE]);
                const ulonglong2* hB = (const ulonglong2*)(&h1bc[p][1 * ASTRIDE]);
                const ulonglong2* hC = (const ulonglong2*)(&h1bc[p][2 * ASTRIDE]);
                const ulonglong2* hD = (const ulonglong2*)(&h1bc[p][3 * ASTRIDE]);
                u64 a0 = 0, a1 = 0, a2 = 0, a3 = 0;
                #pragma unroll
                for (int k = 0; k < 32; k++) {
                    int ki = k + (k >= 16 ? 1 : 0);
                    ulonglong2 v0 = hA[ki], v1 = hB[ki], v2 = hC[ki], v3 = hD[ki];
                    u64 wa = w1[2 * k], wb = w1[2 * k + 1];
                    a0 = ffma2(wa, v0.x, a0); a0 = ffma2(wb, v0.y, a0);
                    a1 = ffma2(wa, v1.x, a1); a1 = ffma2(wb, v1.y, a1);
                    a2 = ffma2(wa, v2.x, a2); a2 = ffma2(wb, v2.y, a2);
                    a3 = ffma2(wa, v3.x, a3); a3 = ffma2(wb, v3.y, a3);
                }
                g1buf[lt * GSTRIDE + 0] = sum2(a0);
                g1buf[lt * GSTRIDE + 1] = sum2(a1);
                g1buf[lt * GSTRIDE + 2] = sum2(a2);
                g1buf[lt * GSTRIDE + 3] = sum2(a3);
            }
            asm volatile("bar.sync 1, 128;" ::: "memory");
            if (i > 0) mbar_wait(mb2a, (uint32_t)((i - 1) & 1));  // WAR cover for B's reads

            // cell1 (step i)
            {
                float gi = g1buf[(cu)      * GSTRIDE + cb] + fmaf(wih1s[cu],      xv, bias1s[cu]);
                float gf = g1buf[(32 + cu) * GSTRIDE + cb] + fmaf(wih1s[32 + cu], xv, bias1s[32 + cu]);
                float gg = g1buf[(64 + cu) * GSTRIDE + cb] + fmaf(wih1s[64 + cu], xv, bias1s[64 + cu]);
                float go = g1buf[(96 + cu) * GSTRIDE + cb] + fmaf(wih1s[96 + cu], xv, bias1s[96 + cu]);
                c1s = sigm(gf) * c1s + sigm(gi) * tanh_fast(gg);
                float h1n = sigm(go) * tanh_fast(c1s);
                #pragma unroll
                for (int r = 0; r < 4; r++) {
                    st_cluster_f32(&h1bc[pn][cb * ASTRIDE + pos], r, h1n);
                    st_cluster_f32(&c1bc[pn][cb * ASTRIDE + pos], r, c1s);
                }
            }
            asm volatile("bar.sync 1, 128;" ::: "memory");
            if (lt < 4) mbar_arrive_rank(mb1a, lt);
        }
    } else {
        // ============================ GROUP B ============================
        const int u  = lt >> 1;
        const int kh = lt & 1;
        const int r0 = 2 * u, r1 = 2 * u + 1;
        float c2s = 0.f;
        float* gh2p = g_h2 + (size_t)(bg0 + cb) * HDIM + slot;

        if (lt < 4) mbar_arrive_rank(mb2a, lt);   // iteration-0 arrive
        for (int i = 1; i <= TSEQ; i++) {
            const int p  = i & 1;
            const int pn = p ^ 1;
            const uint32_t wpar = (uint32_t)((i - 1) & 1);
            mbar_wait(mb1a, wpar);   // c1(i-1) data
            mbar_wait(mb2a, wpar);   // h2(i-2) data + own WAR

            // mv2: gates2(step i-1) rows r0,r1 = Wih2.c1(i-1) + Whh2.h2(i-2), kh half
            {
                const ulonglong2* wi0 = (const ulonglong2*)(sW2 + r0 * WSTRIDE + kh * 68);
                const ulonglong2* wi1 = (const ulonglong2*)(sW2 + r1 * WSTRIDE + kh * 68);
                const ulonglong2* wh0 = (const ulonglong2*)(sW2 + (128 + r0) * WSTRIDE + kh * 68);
                const ulonglong2* wh1 = (const ulonglong2*)(sW2 + (128 + r1) * WSTRIDE + kh * 68);
                const ulonglong2* cA = (const ulonglong2*)(&c1bc[p][0 * ASTRIDE + kh * 68]);
                const ulonglong2* cB = (const ulonglong2*)(&c1bc[p][1 * ASTRIDE + kh * 68]);
                const ulonglong2* cC = (const ulonglong2*)(&c1bc[p][2 * ASTRIDE + kh * 68]);
                const ulonglong2* cD = (const ulonglong2*)(&c1bc[p][3 * ASTRIDE + kh * 68]);
                const ulonglong2* hA = (const ulonglong2*)(&h2bc[p][0 * ASTRIDE + kh * 68]);
                const ulonglong2* hB = (const ulonglong2*)(&h2bc[p][1 * ASTRIDE + kh * 68]);
                const ulonglong2* hC = (const ulonglong2*)(&h2bc[p][2 * ASTRIDE + kh * 68]);
                const ulonglong2* hD = (const ulonglong2*)(&h2bc[p][3 * ASTRIDE + kh * 68]);
                u64 p00 = 0, p01 = 0, p02 = 0, p03 = 0;
                u64 p10 = 0, p11 = 0, p12 = 0, p13 = 0;
                #pragma unroll
                for (int k = 0; k < 16; k++) {
                    ulonglong2 wiA = wi0[k], wiB = wi1[k];
                    ulonglong2 whA = wh0[k], whB = wh1[k];
                    ulonglong2 v0 = cA[k], v1 = cB[k], v2 = cC[k], v3 = cD[k];
                    ulonglong2 u0 = hA[k], u1 = hB[k], u2 = hC[k], u3 = hD[k];
                    p00 = ffma2(wiA.x, v0.x, p00); p00 = ffma2(wiA.y, v0.y, p00);
                    p00 = ffma2(whA.x, u0.x, p00); p00 = ffma2(whA.y, u0.y, p00);
                    p01 = ffma2(wiA.x, v1.x, p01); p01 = ffma2(wiA.y, v1.y, p01);
                    p01 = ffma2(whA.x, u1.x, p01); p01 = ffma2(whA.y, u1.y, p01);
                    p02 = ffma2(wiA.x, v2.x, p02); p02 = ffma2(wiA.y, v2.y, p02);
                    p02 = ffma2(whA.x, u2.x, p02); p02 = ffma2(whA.y, u2.y, p02);
                    p03 = ffma2(wiA.x, v3.x, p03); p03 = ffma2(wiA.y, v3.y, p03);
                    p03 = ffma2(whA.x, u3.x, p03); p03 = ffma2(whA.y, u3.y, p03);
                    p10 = ffma2(wiB.x, v0.x, p10); p10 = ffma2(wiB.y, v0.y, p10);
                    p10 = ffma2(whB.x, u0.x, p10); p10 = ffma2(whB.y, u0.y, p10);
                    p11 = ffma2(wiB.x, v1.x, p11); p11 = ffma2(wiB.y, v1.y, p11);
                    p11 = ffma2(whB.x, u1.x, p11); p11 = ffma2(whB.y, u1.y, p11);
                    p12 = ffma2(wiB.x, v2.x, p12); p12 = ffma2(wiB.y, v2.y, p12);
                    p12 = ffma2(whB.x, u2.x, p12); p12 = ffma2(whB.y, u2.y, p12);
                    p13 = ffma2(wiB.x, v3.x, p13); p13 = ffma2(wiB.y, v3.y, p13);
                    p13 = ffma2(whB.x, u3.x, p13); p13 = ffma2(whB.y, u3.y, p13);
                }
                float s00 = sum2(p00), s01 = sum2(p01), s02 = sum2(p02), s03 = sum2(p03);
                float s10 = sum2(p10), s11 = sum2(p11), s12 = sum2(p12), s13 = sum2(p13);
                s00 += __shfl_xor_sync(0xffffffffu, s00, 1);
                s01 += __shfl_xor_sync(0xffffffffu, s01, 1);
                s02 += __shfl_xor_sync(0xffffffffu, s02, 1);
                s03 += __shfl_xor_sync(0xffffffffu, s03, 1);
                s10 += __shfl_xor_sync(0xffffffffu, s10, 1);
                s11 += __shfl_xor_sync(0xffffffffu, s11, 1);
                s12 += __shfl_xor_sync(0xffffffffu, s12, 1);
                s13 += __shfl_xor_sync(0xffffffffu, s13, 1);
                if (kh == 0) {
                    float* q0 = &g2buf[r0 * GSTRIDE];
                    float* q1 = &g2buf[r1 * GSTRIDE];
                    q0[0] = s00; q0[1] = s01; q0[2] = s02; q0[3] = s03;
                    q1[0] = s10; q1[1] = s11; q1[2] = s12; q1[3] = s13;
                }
            }
            asm volatile("bar.sync 2, 128;" ::: "memory");

            // cell2 (step i-1)
            {
                float gi = g2buf[(cu)      * GSTRIDE + cb] + bias2s[cu];
                float gf = g2buf[(32 + cu) * GSTRIDE + cb] + bias2s[32 + cu];
                float gg = g2buf[(64 + cu) * GSTRIDE + cb] + bias2s[64 + cu];
                float go = g2buf[(96 + cu) * GSTRIDE + cb] + bias2s[96 + cu];
                c2s = sigm(gf) * c2s + sigm(gi) * tanh_fast(gg);
                float h2n = sigm(go) * tanh_fast(c2s);
                if (i < TSEQ) {
                    #pragma unroll
                    for (int r = 0; r < 4; r++)
                        st_cluster_f32(&h2bc[pn][cb * ASTRIDE + pos], r, h2n);
                }
                gh2p[(size_t)(i - 1) * (BATCH * HDIM)] = h2n;
            }
            asm volatile("bar.sync 2, 128;" ::: "memory");
            if (lt < 4 && i < TSEQ) mbar_arrive_rank(mb2a, lt);
        }
    }
}

// ---------------------------------------------------------------------------
__global__ void dots_kernel(const float* __restrict__ w_t)
{
    int gid  = blockIdx.x * blockDim.x + threadIdx.x;
    int gw   = gid >> 5;
    int lane = gid & 31;
    if (gw >= TSEQ * BATCH) return;
    float4 h = *(const float4*)(g_h2 + (size_t)gw * HDIM + lane * 4);
    float4 a = *(const float4*)(w_t + lane * 4);
    float4 o = *(const float4*)(w_t + HDIM + lane * 4);
    float dh   = h.x * a.x + h.y * a.y + h.z * a.z + h.w * a.w;
    float dold = h.x * o.x + h.y * o.y + h.z * o.z + h.w * o.w;
    #pragma unroll
    for (int off = 16; off; off >>= 1) {
        dh   += __shfl_down_sync(0xffffffffu, dh, off);
        dold += __shfl_down_sync(0xffffffffu, dold, off);
    }
    if (lane == 0) { g_dh[gw] = dh; g_dold[gw] = dold; }
}

// ---------------------------------------------------------------------------
// Phase 2b (R13/R11, measured best): per-t softmax + attention + scalar-FMA FC
// ---------------------------------------------------------------------------
__global__ void __launch_bounds__(256, 1)
attn_fc_kernel(const float* __restrict__ fcW, const float* __restrict__ fcb,
               float* __restrict__ out)
{
    extern __shared__ float sm[];
    float* sFcT = sm;                       // [128][132]
    float* sPre = sFcT + 128 * RSTRIDE;     // [128][132]
    float* sE   = sPre + 128 * RSTRIDE;     // [33][128]
    float* sHd  = sE + 33 * 128;            // [128]
    float* sFcb = sHd + 128;                // [128]
    float* sRed = sFcb + 128;               // [256]

    const int t    = blockIdx.x;
    const int tid  = threadIdx.x;
    const int lane = tid & 31;
    const int warp = tid >> 5;

    for (int idx = tid; idx < 128 * 128; idx += 256) {
        int c = idx >> 7, h = idx & 127;
        sFcT[h * RSTRIDE + c] = fcW[idx];
    }
    if (tid < 128) {
        sFcb[tid] = fcb[tid];
        sHd[tid]  = g_dh[t * BATCH + tid];
    }
    __syncthreads();

    const int s_min = (t < 32) ? (32 - t) : 0;
    const int nsc   = (33 - s_min) * 128;
    float lmax = -1e30f;
    for (int n = tid; n < nsc; n += 256) {
        int s = s_min + (n >> 7), b = n & 127;
        int idx = t - 33 + s;
        float sc = sHd[b] + (idx >= 0 ? g_dold[idx * BATCH + b] : 0.f);
        sE[s * 128 + b] = sc;
        lmax = fmaxf(lmax, sc);
    }
    sRed[tid] = lmax; __syncthreads();
    for (int off = 128; off; off >>= 1) {
        if (tid < off) sRed[tid] = fmaxf(sRed[tid], sRed[tid + off]);
        __syncthreads();
    }
    float mx = sRed[0];
    __syncthreads();
    float lsum = 0.f;
    for (int n = tid; n < nsc; n += 256) {
        int s = s_min + (n >> 7), b = n & 127;
        float e = __expf(sE[s * 128 + b] - mx);
        sE[s * 128 + b] = e;
        lsum += e;
    }
    sRed[tid] = lsum; __syncthreads();
    for (int off = 128; off; off >>= 1) {
        if (tid < off) sRed[tid] += sRed[tid + off];
        __syncthreads();
    }
    float inv = __fdividef(1.f, sRed[0]);
    __syncthreads();

    const int s_att = (t < 33) ? (33 - t) : 0;
    for (int b = warp; b < 128; b += 8) {
        float4 acc; acc.x = acc.y = acc.z = acc.w = 0.f;
        for (int s = s_att; s < 33; s++) {
            float w  = sE[s * 128 + b];
            float4 v = *(const float4*)(g_h2 + (size_t)(t - 33 + s) * (BATCH * HDIM)
                                              + (size_t)b * HDIM + lane * 4);
            acc.x += w * v.x; acc.y += w * v.y; acc.z += w * v.z; acc.w += w * v.w;
        }
        float4 hc = *(const float4*)(g_h2 + (size_t)t * (BATCH * HDIM)
                                           + (size_t)b * HDIM + lane * 4);
        float4 pre;
        pre.x = hc.x + inv * acc.x; pre.y = hc.y + inv * acc.y;
        pre.z = hc.z + inv * acc.z; pre.w = hc.w + inv * acc.w;
        *(float4*)(sPre + b * RSTRIDE + lane * 4) = pre;
    }
    __syncthreads();

    const int c0 = lane * 4;
    float4 bias = *(const float4*)(sFcb + c0);
    for (int r = 0; r < 4; r++) {
        int b0 = (warp + 8 * r) * 4;
        float4 a0, a1, a2, a3;
        a0.x=a0.y=a0.z=a0.w=0.f; a1=a0; a2=a0; a3=a0;
        const float4* p0 = (const float4*)(sPre + (size_t)(b0 + 0) * RSTRIDE);
        const float4* p1 = (const float4*)(sPre + (size_t)(b0 + 1) * RSTRIDE);
        const float4* p2 = (const float4*)(sPre + (size_t)(b0 + 2) * RSTRIDE);
        const float4* p3 = (const float4*)(sPre + (size_t)(b0 + 3) * RSTRIDE);
        #pragma unroll
        for (int h4 = 0; h4 < 32; h4++) {
            float4 q0 = p0[h4], q1 = p1[h4], q2 = p2[h4], q3 = p3[h4];
            #pragma unroll
            for (int hh = 0; hh < 4; hh++) {
                float4 w = *(const float4*)(sFcT + (h4 * 4 + hh) * RSTRIDE + c0);
                float v0 = (&q0.x)[hh], v1 = (&q1.x)[hh], v2 = (&q2.x)[hh], v3 = (&q3.x)[hh];
                a0.x += v0 * w.x; a0.y += v0 * w.y; a0.z += v0 * w.z; a0.w += v0 * w.w;
                a1.x += v1 * w.x; a1.y += v1 * w.y; a1.z += v1 * w.z; a1.w += v1 * w.w;
                a2.x += v2 * w.x; a2.y += v2 * w.y; a2.z += v2 * w.z; a2.w += v2 * w.w;
                a3.x += v3 * w.x; a3.y += v3 * w.y; a3.z += v3 * w.z; a3.w += v3 * w.w;
            }
        }
        a0.x += bias.x; a0.y += bias.y; a0.z += bias.z; a0.w += bias.w;
        a1.x += bias.x; a1.y += bias.y; a1.z += bias.z; a1.w += bias.w;
        a2.x += bias.x; a2.y += bias.y; a2.z += bias.z; a2.w += bias.w;
        a3.x += bias.x; a3.y += bias.y; a3.z += bias.z; a3.w += bias.w;
        size_t obase = (size_t)t * 128 + c0;
        *(float4*)(out + (size_t)(b0 + 0) * (TSEQ * 128) + obase) = a0;
        *(float4*)(out + (size_t)(b0 + 1) * (TSEQ * 128) + obase) = a1;
        *(float4*)(out + (size_t)(b0 + 2) * (TSEQ * 128) + obase) = a2;
        *(float4*)(out + (size_t)(b0 + 3) * (TSEQ * 128) + obase) = a3;
    }
}

// ---------------------------------------------------------------------------
extern "C" void kernel_launch(void* const* d_in, const int* in_sizes, int n_in,
                              void* d_out, int out_size)
{
    const float* x    = (const float*)d_in[0];
    const float* Wih1 = (const float*)d_in[1];
    const float* Whh1 = (const float*)d_in[2];
    const float* bih1 = (const float*)d_in[3];
    const float* bhh1 = (const float*)d_in[4];
    const float* Wih2 = (const float*)d_in[5];
    const float* Whh2 = (const float*)d_in[6];
    const float* bih2 = (const float*)d_in[7];
    const float* bhh2 = (const float*)d_in[8];
    const float* w_t  = (const float*)d_in[9];
    const float* fcW  = (const float*)d_in[10];
    const float* fcb  = (const float*)d_in[11];
    float* out = (float*)d_out;

    const int smem1 = 256 * WSTRIDE * (int)sizeof(float);   // 135168
    const int smem3 = (2 * 128 * RSTRIDE + 33 * 128 + 128 + 128 + 256) * (int)sizeof(float);

    cudaFuncSetAttribute(lstm_seq_kernel, cudaFuncAttributeMaxDynamicSharedMemorySize, smem1);
    cudaFuncSetAttribute(attn_fc_kernel,  cudaFuncAttributeMaxDynamicSharedMemorySize, smem3);

    lstm_seq_kernel<<<128, 256, smem1>>>(x, Wih1, Whh1, bih1, bhh1,
                                         Wih2, Whh2, bih2, bhh2);
    dots_kernel<<<(TSEQ * BATCH * 32) / 256, 256>>>(w_t);
    attn_fc_kernel<<<TSEQ, 256, smem3>>>(fcW, fcb, out);
}

// round 16
// speedup vs baseline: 1.3683x; 1.0111x over previous
#include <cuda_runtime.h>
#include <cstdint>

#define HDIM 128
#define TSEQ 512
#define BATCH 128
#define GB 4
#define RSTRIDE 132
#define WSTRIDE 132
#define ASTRIDE 132     // activation row stride; dims 64..127 live at float-offset 68
#define GSTRIDE 9       // gate-buffer row stride -> conflict-free scalar access

typedef unsigned long long u64;

__device__ float g_h2[(size_t)TSEQ * BATCH * HDIM];   // [t][b][h]
__device__ float g_dold[TSEQ * BATCH];
__device__ float g_dh[TSEQ * BATCH];

// HW tanh (MUFU.TANH, sm_75+): single instruction, ~2^-11 rel err.
__device__ __forceinline__ float tanh_a(float x) {
    float r;
    asm("tanh.approx.f32 %0, %1;" : "=f"(r) : "f"(x));
    return r;
}
__device__ __forceinline__ float sigm(float x) {
    return fmaf(0.5f, tanh_a(0.5f * x), 0.5f);
}
__device__ __forceinline__ u64 ffma2(u64 a, u64 b, u64 c) {
    u64 d;
    asm("fma.rn.f32x2 %0, %1, %2, %3;" : "=l"(d) : "l"(a), "l"(b), "l"(c));
    return d;
}
__device__ __forceinline__ float sum2(u64 v) {
    float lo, hi;
    asm("mov.b64 {%0, %1}, %2;" : "=f"(lo), "=f"(hi) : "l"(v));
    return lo + hi;
}
__device__ __forceinline__ void st_cluster_f32(float* p, int rank, float v) {
    uint32_t la = (uint32_t)__cvta_generic_to_shared(p);
    uint32_t ra;
    asm volatile("mapa.shared::cluster.u32 %0, %1, %2;" : "=r"(ra) : "r"(la), "r"(rank));
    asm volatile("st.shared::cluster.f32 [%0], %1;" :: "r"(ra), "f"(v) : "memory");
}
__device__ __forceinline__ void mbar_init(uint32_t a, uint32_t cnt) {
    asm volatile("mbarrier.init.shared.b64 [%0], %1;" :: "r"(a), "r"(cnt) : "memory");
}
__device__ __forceinline__ void mbar_arrive_rank(uint32_t local_addr, uint32_t rank) {
    asm volatile(
        "{\n\t.reg .b32 ra;\n\t"
        "mapa.shared::cluster.u32 ra, %0, %1;\n\t"
        "mbarrier.arrive.release.cluster.shared::cluster.b64 _, [ra];\n\t}"
        :: "r"(local_addr), "r"(rank) : "memory");
}
__device__ __forceinline__ void mbar_wait(uint32_t addr, uint32_t parity) {
    asm volatile(
        "{\n\t.reg .pred P;\n"
        "WL_%=:\n\t"
        "mbarrier.try_wait.parity.acquire.cluster.shared::cta.b64 P, [%0], %1, 0x989680;\n\t"
        "@P bra WD_%=;\n\t"
        "bra WL_%=;\n"
        "WD_%=:\n\t}"
        :: "r"(addr), "r"(parity) : "memory");
}
__device__ __forceinline__ void cluster_sync_() {
    asm volatile("barrier.cluster.arrive.aligned;" ::: "memory");
    asm volatile("barrier.cluster.wait.aligned;" ::: "memory");
}

// ---------------------------------------------------------------------------
// Phase 1 (R15 + HW tanh activations): layer-split warp specialization.
// ---------------------------------------------------------------------------
__global__ void __launch_bounds__(256, 1) __cluster_dims__(4, 1, 1)
lstm_seq_kernel(const float* __restrict__ x,
                const float* __restrict__ Wih1, const float* __restrict__ Whh1,
                const float* __restrict__ bih1, const float* __restrict__ bhh1,
                const float* __restrict__ Wih2, const float* __restrict__ Whh2,
                const float* __restrict__ bih2, const float* __restrict__ bhh2)
{
    extern __shared__ float sW2[];   // [256][WSTRIDE] rows 0-127 Wih2, 128-255 Whh2; kh-gap cols

    __shared__ __align__(16) float h1bc[2][GB * ASTRIDE];
    __shared__ __align__(16) float c1bc[2][GB * ASTRIDE];
    __shared__ __align__(16) float h2bc[2][GB * ASTRIDE];
    __shared__ float xs[GB][TSEQ];
    __shared__ float g1buf[128 * GSTRIDE];
    __shared__ float g2buf[128 * GSTRIDE];
    __shared__ float bias1s[128], bias2s[128], wih1s[128];
    __shared__ __align__(8) u64 mbar[2];

    const int tid  = threadIdx.x;
    const int rank = blockIdx.x & 3;
    const int bg0  = (blockIdx.x >> 2) * GB;
    const int lt   = tid & 127;

    const int cu   = lt & 31, cb = lt >> 5;
    const int slot = rank * 32 + cu;
    const int pos  = slot + (slot >= 64 ? 4 : 0);

    u64 w1[64];
    if (tid < 128) {
        const int gr = (lt >> 5) * 128 + rank * 32 + (lt & 31);
        const float* src = Whh1 + (size_t)gr * 128;
        #pragma unroll
        for (int k = 0; k < 32; k++) {
            ulonglong2 v = ((const ulonglong2*)src)[k];
            w1[2 * k] = v.x; w1[2 * k + 1] = v.y;
        }
    }

    for (int idx = tid; idx < 256 * 32; idx += 256) {
        int j = idx >> 5, k4 = idx & 31;
        int jr = j & 127;
        int gr = (jr >> 5) * 128 + rank * 32 + (jr & 31);
        const float* src = ((j >> 7) ? Whh2 : Wih2) + (size_t)gr * 128 + k4 * 4;
        int dstc = (k4 < 16) ? (k4 * 4) : (k4 * 4 + 4);
        *(float4*)(sW2 + j * WSTRIDE + dstc) = *(const float4*)src;
    }
    if (tid < 128) {
        int gr = (tid >> 5) * 128 + rank * 32 + (tid & 31);
        bias1s[tid] = bih1[gr] + bhh1[gr];
        bias2s[tid] = bih2[gr] + bhh2[gr];
        wih1s[tid]  = Wih1[gr];
    }
    for (int idx = tid; idx < GB * TSEQ; idx += 256) {
        int b = idx >> 9, tt = idx & (TSEQ - 1);
        xs[b][tt] = x[(size_t)(bg0 + b) * TSEQ + tt];
    }
    for (int idx = tid; idx < 2 * GB * ASTRIDE; idx += 256) {
        ((float*)h1bc)[idx] = 0.f;
        ((float*)c1bc)[idx] = 0.f;
        ((float*)h2bc)[idx] = 0.f;
    }
    const uint32_t mb1a = (uint32_t)__cvta_generic_to_shared(&mbar[0]);
    const uint32_t mb2a = (uint32_t)__cvta_generic_to_shared(&mbar[1]);
    if (tid == 0) { mbar_init(mb1a, 4); mbar_init(mb2a, 4); }
    __syncthreads();
    cluster_sync_();

    if (tid < 128) {
        // ============================ GROUP A ============================
        float c1s = 0.f;
        for (int i = 0; i < TSEQ; i++) {
            const int p  = i & 1;
            const int pn = p ^ 1;
            if (i > 0) mbar_wait(mb1a, (uint32_t)((i - 1) & 1));

            float xv = xs[cb][i];   // hoisted: latency hidden under mv1

            {
                const ulonglong2* hA = (const ulonglong2*)(&h1bc[p][0 * ASTRIDE]);
                const ulonglong2* hB = (const ulonglong2*)(&h1bc[p][1 * ASTRIDE]);
                const ulonglong2* hC = (const ulonglong2*)(&h1bc[p][2 * ASTRIDE]);
                const ulonglong2* hD = (const ulonglong2*)(&h1bc[p][3 * ASTRIDE]);
                u64 a0 = 0, a1 = 0, a2 = 0, a3 = 0;
                #pragma unroll
                for (int k = 0; k < 32; k++) {
                    int ki = k + (k >= 16 ? 1 : 0);
                    ulonglong2 v0 = hA[ki], v1 = hB[ki], v2 = hC[ki], v3 = hD[ki];
                    u64 wa = w1[2 * k], wb = w1[2 * k + 1];
                    a0 = ffma2(wa, v0.x, a0); a0 = ffma2(wb, v0.y, a0);
                    a1 = ffma2(wa, v1.x, a1); a1 = ffma2(wb, v1.y, a1);
                    a2 = ffma2(wa, v2.x, a2); a2 = ffma2(wb, v2.y, a2);
                    a3 = ffma2(wa, v3.x, a3); a3 = ffma2(wb, v3.y, a3);
                }
                g1buf[lt * GSTRIDE + 0] = sum2(a0);
                g1buf[lt * GSTRIDE + 1] = sum2(a1);
                g1buf[lt * GSTRIDE + 2] = sum2(a2);
                g1buf[lt * GSTRIDE + 3] = sum2(a3);
            }
            asm volatile("bar.sync 1, 128;" ::: "memory");
            if (i > 0) mbar_wait(mb2a, (uint32_t)((i - 1) & 1));

            // cell1 (step i)
            {
                float gi = g1buf[(cu)      * GSTRIDE + cb] + fmaf(wih1s[cu],      xv, bias1s[cu]);
                float gf = g1buf[(32 + cu) * GSTRIDE + cb] + fmaf(wih1s[32 + cu], xv, bias1s[32 + cu]);
                float gg = g1buf[(64 + cu) * GSTRIDE + cb] + fmaf(wih1s[64 + cu], xv, bias1s[64 + cu]);
                float go = g1buf[(96 + cu) * GSTRIDE + cb] + fmaf(wih1s[96 + cu], xv, bias1s[96 + cu]);
                c1s = sigm(gf) * c1s + sigm(gi) * tanh_a(gg);
                float h1n = sigm(go) * tanh_a(c1s);
                #pragma unroll
                for (int r = 0; r < 4; r++) {
                    st_cluster_f32(&h1bc[pn][cb * ASTRIDE + pos], r, h1n);
                    st_cluster_f32(&c1bc[pn][cb * ASTRIDE + pos], r, c1s);
                }
            }
            asm volatile("bar.sync 1, 128;" ::: "memory");
            if (lt < 4) mbar_arrive_rank(mb1a, lt);
        }
    } else {
        // ============================ GROUP B ============================
        const int u  = lt >> 1;
        const int kh = lt & 1;
        const int r0 = 2 * u, r1 = 2 * u + 1;
        float c2s = 0.f;
        float* gh2p = g_h2 + (size_t)(bg0 + cb) * HDIM + slot;

        if (lt < 4) mbar_arrive_rank(mb2a, lt);   // iteration-0 arrive
        for (int i = 1; i <= TSEQ; i++) {
            const int p  = i & 1;
            const int pn = p ^ 1;
            const uint32_t wpar = (uint32_t)((i - 1) & 1);
            mbar_wait(mb1a, wpar);
            mbar_wait(mb2a, wpar);

            {
                const ulonglong2* wi0 = (const ulonglong2*)(sW2 + r0 * WSTRIDE + kh * 68);
                const ulonglong2* wi1 = (const ulonglong2*)(sW2 + r1 * WSTRIDE + kh * 68);
                const ulonglong2* wh0 = (const ulonglong2*)(sW2 + (128 + r0) * WSTRIDE + kh * 68);
                const ulonglong2* wh1 = (const ulonglong2*)(sW2 + (128 + r1) * WSTRIDE + kh * 68);
                const ulonglong2* cA = (const ulonglong2*)(&c1bc[p][0 * ASTRIDE + kh * 68]);
                const ulonglong2* cB = (const ulonglong2*)(&c1bc[p][1 * ASTRIDE + kh * 68]);
                const ulonglong2* cC = (const ulonglong2*)(&c1bc[p][2 * ASTRIDE + kh * 68]);
                const ulonglong2* cD = (const ulonglong2*)(&c1bc[p][3 * ASTRIDE + kh * 68]);
                const ulonglong2* hA = (const ulonglong2*)(&h2bc[p][0 * ASTRIDE + kh * 68]);
                const ulonglong2* hB = (const ulonglong2*)(&h2bc[p][1 * ASTRIDE + kh * 68]);
                const ulonglong2* hC = (const ulonglong2*)(&h2bc[p][2 * ASTRIDE + kh * 68]);
                const ulonglong2* hD = (const ulonglong2*)(&h2bc[p][3 * ASTRIDE + kh * 68]);
                u64 p00 = 0, p01 = 0, p02 = 0, p03 = 0;
                u64 p10 = 0, p11 = 0, p12 = 0, p13 = 0;
                #pragma unroll
                for (int k = 0; k < 16; k++) {
                    ulonglong2 wiA = wi0[k], wiB = wi1[k];
                    ulonglong2 whA = wh0[k], whB = wh1[k];
                    ulonglong2 v0 = cA[k], v1 = cB[k], v2 = cC[k], v3 = cD[k];
                    ulonglong2 u0 = hA[k], u1 = hB[k], u2 = hC[k], u3 = hD[k];
                    p00 = ffma2(wiA.x, v0.x, p00); p00 = ffma2(wiA.y, v0.y, p00);
                    p00 = ffma2(whA.x, u0.x, p00); p00 = ffma2(whA.y, u0.y, p00);
                    p01 = ffma2(wiA.x, v1.x, p01); p01 = ffma2(wiA.y, v1.y, p01);
                    p01 = ffma2(whA.x, u1.x, p01); p01 = ffma2(whA.y, u1.y, p01);
                    p02 = ffma2(wiA.x, v2.x, p02); p02 = ffma2(wiA.y, v2.y, p02);
                    p02 = ffma2(whA.x, u2.x, p02); p02 = ffma2(whA.y, u2.y, p02);
                    p03 = ffma2(wiA.x, v3.x, p03); p03 = ffma2(wiA.y, v3.y, p03);
                    p03 = ffma2(whA.x, u3.x, p03); p03 = ffma2(whA.y, u3.y, p03);
                    p10 = ffma2(wiB.x, v0.x, p10); p10 = ffma2(wiB.y, v0.y, p10);
                    p10 = ffma2(whB.x, u0.x, p10); p10 = ffma2(whB.y, u0.y, p10);
                    p11 = ffma2(wiB.x, v1.x, p11); p11 = ffma2(wiB.y, v1.y, p11);
                    p11 = ffma2(whB.x, u1.x, p11); p11 = ffma2(whB.y, u1.y, p11);
                    p12 = ffma2(wiB.x, v2.x, p12); p12 = ffma2(wiB.y, v2.y, p12);
                    p12 = ffma2(whB.x, u2.x, p12); p12 = ffma2(whB.y, u2.y, p12);
                    p13 = ffma2(wiB.x, v3.x, p13); p13 = ffma2(wiB.y, v3.y, p13);
                    p13 = ffma2(whB.x, u3.x, p13); p13 = ffma2(whB.y, u3.y, p13);
                }
                float s00 = sum2(p00), s01 = sum2(p01), s02 = sum2(p02), s03 = sum2(p03);
                float s10 = sum2(p10), s11 = sum2(p11), s12 = sum2(p12), s13 = sum2(p13);
                s00 += __shfl_xor_sync(0xffffffffu, s00, 1);
                s01 += __shfl_xor_sync(0xffffffffu, s01, 1);
                s02 += __shfl_xor_sync(0xffffffffu, s02, 1);
                s03 += __shfl_xor_sync(0xffffffffu, s03, 1);
                s10 += __shfl_xor_sync(0xffffffffu, s10, 1);
                s11 += __shfl_xor_sync(0xffffffffu, s11, 1);
                s12 += __shfl_xor_sync(0xffffffffu, s12, 1);
                s13 += __shfl_xor_sync(0xffffffffu, s13, 1);
                if (kh == 0) {
                    float* q0 = &g2buf[r0 * GSTRIDE];
                    float* q1 = &g2buf[r1 * GSTRIDE];
                    q0[0] = s00; q0[1] = s01; q0[2] = s02; q0[3] = s03;
                    q1[0] = s10; q1[1] = s11; q1[2] = s12; q1[3] = s13;
                }
            }
            asm volatile("bar.sync 2, 128;" ::: "memory");

            // cell2 (step i-1)
            {
                float gi = g2buf[(cu)      * GSTRIDE + cb] + bias2s[cu];
                float gf = g2buf[(32 + cu) * GSTRIDE + cb] + bias2s[32 + cu];
                float gg = g2buf[(64 + cu) * GSTRIDE + cb] + bias2s[64 + cu];
                float go = g2buf[(96 + cu) * GSTRIDE + cb] + bias2s[96 + cu];
                c2s = sigm(gf) * c2s + sigm(gi) * tanh_a(gg);
                float h2n = sigm(go) * tanh_a(c2s);
                if (i < TSEQ) {
                    #pragma unroll
                    for (int r = 0; r < 4; r++)
                        st_cluster_f32(&h2bc[pn][cb * ASTRIDE + pos], r, h2n);
                }
                gh2p[(size_t)(i - 1) * (BATCH * HDIM)] = h2n;
            }
            asm volatile("bar.sync 2, 128;" ::: "memory");
            if (lt < 4 && i < TSEQ) mbar_arrive_rank(mb2a, lt);
        }
    }
}

// ---------------------------------------------------------------------------
__global__ void dots_kernel(const float* __restrict__ w_t)
{
    int gid  = blockIdx.x * blockDim.x + threadIdx.x;
    int gw   = gid >> 5;
    int lane = gid & 31;
    if (gw >= TSEQ * BATCH) return;
    float4 h = *(const float4*)(g_h2 + (size_t)gw * HDIM + lane * 4);
    float4 a = *(const float4*)(w_t + lane * 4);
    float4 o = *(const float4*)(w_t + HDIM + lane * 4);
    float dh   = h.x * a.x + h.y * a.y + h.z * a.z + h.w * a.w;
    float dold = h.x * o.x + h.y * o.y + h.z * o.z + h.w * o.w;
    #pragma unroll
    for (int off = 16; off; off >>= 1) {
        dh   += __shfl_down_sync(0xffffffffu, dh, off);
        dold += __shfl_down_sync(0xffffffffu, dold, off);
    }
    if (lane == 0) { g_dh[gw] = dh; g_dold[gw] = dold; }
}

// ---------------------------------------------------------------------------
__global__ void __launch_bounds__(256, 1)
attn_fc_kernel(const float* __restrict__ fcW, const float* __restrict__ fcb,
               float* __restrict__ out)
{
    extern __shared__ float sm[];
    float* sFcT = sm;                       // [128][132]
    float* sPre = sFcT + 128 * RSTRIDE;     // [128][132]
    float* sE   = sPre + 128 * RSTRIDE;     // [33][128]
    float* sHd  = sE + 33 * 128;            // [128]
    float* sFcb = sHd + 128;                // [128]
    float* sRed = sFcb + 128;               // [256]

    const int t    = blockIdx.x;
    const int tid  = threadIdx.x;
    const int lane = tid & 31;
    const int warp = tid >> 5;

    for (int idx = tid; idx < 128 * 128; idx += 256) {
        int c = idx >> 7, h = idx & 127;
        sFcT[h * RSTRIDE + c] = fcW[idx];
    }
    if (tid < 128) {
        sFcb[tid] = fcb[tid];
        sHd[tid]  = g_dh[t * BATCH + tid];
    }
    __syncthreads();

    const int s_min = (t < 32) ? (32 - t) : 0;
    const int nsc   = (33 - s_min) * 128;
    float lmax = -1e30f;
    for (int n = tid; n < nsc; n += 256) {
        int s = s_min + (n >> 7), b = n & 127;
        int idx = t - 33 + s;
        float sc = sHd[b] + (idx >= 0 ? g_dold[idx * BATCH + b] : 0.f);
        sE[s * 128 + b] = sc;
        lmax = fmaxf(lmax, sc);
    }
    sRed[tid] = lmax; __syncthreads();
    for (int off = 128; off; off >>= 1) {
        if (tid < off) sRed[tid] = fmaxf(sRed[tid], sRed[tid + off]);
        __syncthreads();
    }
    float mx = sRed[0];
    __syncthreads();
    float lsum = 0.f;
    for (int n = tid; n < nsc; n += 256) {
        int s = s_min + (n >> 7), b = n & 127;
        float e = __expf(sE[s * 128 + b] - mx);
        sE[s * 128 + b] = e;
        lsum += e;
    }
    sRed[tid] = lsum; __syncthreads();
    for (int off = 128; off; off >>= 1) {
        if (tid < off) sRed[tid] += sRed[tid + off];
        __syncthreads();
    }
    float inv = __fdividef(1.f, sRed[0]);
    __syncthreads();

    const int s_att = (t < 33) ? (33 - t) : 0;
    for (int b = warp; b < 128; b += 8) {
        float4 acc; acc.x = acc.y = acc.z = acc.w = 0.f;
        for (int s = s_att; s < 33; s++) {
            float w  = sE[s * 128 + b];
            float4 v = *(const float4*)(g_h2 + (size_t)(t - 33 + s) * (BATCH * HDIM)
                                              + (size_t)b * HDIM + lane * 4);
            acc.x += w * v.x; acc.y += w * v.y; acc.z += w * v.z; acc.w += w * v.w;
        }
        float4 hc = *(const float4*)(g_h2 + (size_t)t * (BATCH * HDIM)
                                           + (size_t)b * HDIM + lane * 4);
        float4 pre;
        pre.x = hc.x + inv * acc.x; pre.y = hc.y + inv * acc.y;
        pre.z = hc.z + inv * acc.z; pre.w = hc.w + inv * acc.w;
        *(float4*)(sPre + b * RSTRIDE + lane * 4) = pre;
    }
    __syncthreads();

    const int c0 = lane * 4;
    float4 bias = *(const float4*)(sFcb + c0);
    for (int r = 0; r < 4; r++) {
        int b0 = (warp + 8 * r) * 4;
        float4 a0, a1, a2, a3;
        a0.x=a0.y=a0.z=a0.w=0.f; a1=a0; a2=a0; a3=a0;
        const float4* p0 = (const float4*)(sPre + (size_t)(b0 + 0) * RSTRIDE);
        const float4* p1 = (const float4*)(sPre + (size_t)(b0 + 1) * RSTRIDE);
        const float4* p2 = (const float4*)(sPre + (size_t)(b0 + 2) * RSTRIDE);
        const float4* p3 = (const float4*)(sPre + (size_t)(b0 + 3) * RSTRIDE);
        #pragma unroll
        for (int h4 = 0; h4 < 32; h4++) {
            float4 q0 = p0[h4], q1 = p1[h4], q2 = p2[h4], q3 = p3[h4];
            #pragma unroll
            for (int hh = 0; hh < 4; hh++) {
                float4 w = *(const float4*)(sFcT + (h4 * 4 + hh) * RSTRIDE + c0);
                float v0 = (&q0.x)[hh], v1 = (&q1.x)[hh], v2 = (&q2.x)[hh], v3 = (&q3.x)[hh];
                a0.x += v0 * w.x; a0.y += v0 * w.y; a0.z += v0 * w.z; a0.w += v0 * w.w;
                a1.x += v1 * w.x; a1.y += v1 * w.y; a1.z += v1 * w.z; a1.w += v1 * w.w;
                a2.x += v2 * w.x; a2.y += v2 * w.y; a2.z += v2 * w.z; a2.w += v2 * w.w;
                a3.x += v3 * w.x; a3.y += v3 * w.y; a3.z += v3 * w.z; a3.w += v3 * w.w;
            }
        }
        a0.x += bias.x; a0.y += bias.y; a0.z += bias.z; a0.w += bias.w;
        a1.x += bias.x; a1.y += bias.y; a1.z += bias.z; a1.w += bias.w;
        a2.x += bias.x; a2.y += bias.y; a2.z += bias.z; a2.w += bias.w;
        a3.x += bias.x; a3.y += bias.y; a3.z += bias.z; a3.w += bias.w;
        size_t obase = (size_t)t * 128 + c0;
        *(float4*)(out + (size_t)(b0 + 0) * (TSEQ * 128) + obase) = a0;
        *(float4*)(out + (size_t)(b0 + 1) * (TSEQ * 128) + obase) = a1;
        *(float4*)(out + (size_t)(b0 + 2) * (TSEQ * 128) + obase) = a2;
        *(float4*)(out + (size_t)(b0 + 3) * (TSEQ * 128) + obase) = a3;
    }
}

// ---------------------------------------------------------------------------
extern "C" void kernel_launch(void* const* d_in, const int* in_sizes, int n_in,
                              void* d_out, int out_size)
{
    const float* x    = (const float*)d_in[0];
    const float* Wih1 = (const float*)d_in[1];
    const float* Whh1 = (const float*)d_in[2];
    const float* bih1 = (const float*)d_in[3];
    const float* bhh1 = (const float*)d_in[4];
    const float* Wih2 = (const float*)d_in[5];
    const float* Whh2 = (const float*)d_in[6];
    const float* bih2 = (const float*)d_in[7];
    const float* bhh2 = (const float*)d_in[8];
    const float* w_t  = (const float*)d_in[9];
    const float* fcW  = (const float*)d_in[10];
    const float* fcb  = (const float*)d_in[11];
    float* out = (float*)d_out;

    const int smem1 = 256 * WSTRIDE * (int)sizeof(float);   // 135168
    const int smem3 = (2 * 128 * RSTRIDE + 33 * 128 + 128 + 128 + 256) * (int)sizeof(float);

    cudaFuncSetAttribute(lstm_seq_kernel, cudaFuncAttributeMaxDynamicSharedMemorySize, smem1);
    cudaFuncSetAttribute(attn_fc_kernel,  cudaFuncAttributeMaxDynamicSharedMemorySize, smem3);

    lstm_seq_kernel<<<128, 256, smem1>>>(x, Wih1, Whh1, bih1, bhh1,
                                         Wih2, Whh2, bih2, bhh2);
    dots_kernel<<<(TSEQ * BATCH * 32) / 256, 256>>>(w_t);
    attn_fc_kernel<<<TSEQ, 256, smem3>>>(fcW, fcb, out);
}

// round 17
// speedup vs baseline: 1.4611x; 1.0678x over previous
#include <cuda_runtime.h>
#include <cstdint>

#define HDIM 128
#define TSEQ 512
#define BATCH 128
#define GB 4
#define RSTRIDE 132
#define WSTRIDE 132
#define ASTRIDE 132     // activation row stride; dims 64..127 live at float-offset 68
#define GSTRIDE 9       // gate-buffer row stride -> conflict-free scalar access

typedef unsigned long long u64;

__device__ float g_h2[(size_t)TSEQ * BATCH * HDIM];   // [t][b][h]
__device__ float g_dold[TSEQ * BATCH];
__device__ float g_dh[TSEQ * BATCH];

__device__ __forceinline__ float tanh_a(float x) {
    float r;
    asm("tanh.approx.f32 %0, %1;" : "=f"(r) : "f"(x));
    return r;
}
__device__ __forceinline__ float sigm(float x) {
    return fmaf(0.5f, tanh_a(0.5f * x), 0.5f);
}
__device__ __forceinline__ u64 ffma2(u64 a, u64 b, u64 c) {
    u64 d;
    asm("fma.rn.f32x2 %0, %1, %2, %3;" : "=l"(d) : "l"(a), "l"(b), "l"(c));
    return d;
}
__device__ __forceinline__ float sum2(u64 v) {
    float lo, hi;
    asm("mov.b64 {%0, %1}, %2;" : "=f"(lo), "=f"(hi) : "l"(v));
    return lo + hi;
}
__device__ __forceinline__ void st_cluster_f32(float* p, int rank, float v) {
    uint32_t la = (uint32_t)__cvta_generic_to_shared(p);
    uint32_t ra;
    asm volatile("mapa.shared::cluster.u32 %0, %1, %2;" : "=r"(ra) : "r"(la), "r"(rank));
    asm volatile("st.shared::cluster.f32 [%0], %1;" :: "r"(ra), "f"(v) : "memory");
}
__device__ __forceinline__ void mbar_init(uint32_t a, uint32_t cnt) {
    asm volatile("mbarrier.init.shared.b64 [%0], %1;" :: "r"(a), "r"(cnt) : "memory");
}
__device__ __forceinline__ void mbar_arrive_rank(uint32_t local_addr, uint32_t rank) {
    asm volatile(
        "{\n\t.reg .b32 ra;\n\t"
        "mapa.shared::cluster.u32 ra, %0, %1;\n\t"
        "mbarrier.arrive.release.cluster.shared::cluster.b64 _, [ra];\n\t}"
        :: "r"(local_addr), "r"(rank) : "memory");
}
__device__ __forceinline__ void mbar_wait(uint32_t addr, uint32_t parity) {
    asm volatile(
        "{\n\t.reg .pred P;\n"
        "WL_%=:\n\t"
        "mbarrier.try_wait.parity.acquire.cluster.shared::cta.b64 P, [%0], %1, 0x989680;\n\t"
        "@P bra WD_%=;\n\t"
        "bra WL_%=;\n"
        "WD_%=:\n\t}"
        :: "r"(addr), "r"(parity) : "memory");
}
__device__ __forceinline__ void cluster_sync_() {
    asm volatile("barrier.cluster.arrive.aligned;" ::: "memory");
    asm volatile("barrier.cluster.wait.aligned;" ::: "memory");
}

// ---------------------------------------------------------------------------
// Phase 1 (R16 + LDS-issue cuts): layer-split warp specialization.
//  Group A: thread = (row-pair 2u,2u+1; k-half kh). W1 half-rows in REGS
//           (same 128 regs as before); act loads/warp drop 132 -> 64
//           (two kh broadcast groups, different banks via gap layout);
//           shfl_xor(16) combines halves.
//  Group B: Wih2 half-rows now in REGS (64 u64 from global); only Whh2
//           stays in SMEM -> weight LDS wavefronts halved.
// ---------------------------------------------------------------------------
__global__ void __launch_bounds__(256, 1) __cluster_dims__(4, 1, 1)
lstm_seq_kernel(const float* __restrict__ x,
                const float* __restrict__ Wih1, const float* __restrict__ Whh1,
                const float* __restrict__ bih1, const float* __restrict__ bhh1,
                const float* __restrict__ Wih2, const float* __restrict__ Whh2,
                const float* __restrict__ bih2, const float* __restrict__ bhh2)
{
    extern __shared__ float sW2[];   // [128][WSTRIDE] Whh2 slice, kh-gap cols

    __shared__ __align__(16) float h1bc[2][GB * ASTRIDE];
    __shared__ __align__(16) float c1bc[2][GB * ASTRIDE];
    __shared__ __align__(16) float h2bc[2][GB * ASTRIDE];
    __shared__ float xs[GB][TSEQ];
    __shared__ float g1buf[128 * GSTRIDE];
    __shared__ float g2buf[128 * GSTRIDE];
    __shared__ float bias1s[128], bias2s[128], wih1s[128];
    __shared__ __align__(8) u64 mbar[2];

    const int tid  = threadIdx.x;
    const int rank = blockIdx.x & 3;
    const int bg0  = (blockIdx.x >> 2) * GB;
    const int lt   = tid & 127;

    const int cu   = lt & 31, cb = lt >> 5;
    const int slot = rank * 32 + cu;
    const int pos  = slot + (slot >= 64 ? 4 : 0);

    // shared role for both groups: u = row-pair id (0..63), kh = k-half
    const int u  = (lt & 15) | ((lt >> 5) << 4);
    const int kh = (lt >> 4) & 1;
    const int r0 = 2 * u, r1 = 2 * u + 1;

    // ---- Whh2 slice -> SMEM (kh-gap column layout)
    for (int idx = tid; idx < 128 * 32; idx += 256) {
        int j = idx >> 5, k4 = idx & 31;
        int gr = (j >> 5) * 128 + rank * 32 + (j & 31);
        const float* src = Whh2 + (size_t)gr * 128 + k4 * 4;
        int dstc = (k4 < 16) ? (k4 * 4) : (k4 * 4 + 4);
        *(float4*)(sW2 + j * WSTRIDE + dstc) = *(const float4*)src;
    }
    if (tid < 128) {
        int gr = (tid >> 5) * 128 + rank * 32 + (tid & 31);
        bias1s[tid] = bih1[gr] + bhh1[gr];
        bias2s[tid] = bih2[gr] + bhh2[gr];
        wih1s[tid]  = Wih1[gr];
    }
    for (int idx = tid; idx < GB * TSEQ; idx += 256) {
        int b = idx >> 9, tt = idx & (TSEQ - 1);
        xs[b][tt] = x[(size_t)(bg0 + b) * TSEQ + tt];
    }
    for (int idx = tid; idx < 2 * GB * ASTRIDE; idx += 256) {
        ((float*)h1bc)[idx] = 0.f;
        ((float*)c1bc)[idx] = 0.f;
        ((float*)h2bc)[idx] = 0.f;
    }
    const uint32_t mb1a = (uint32_t)__cvta_generic_to_shared(&mbar[0]);
    const uint32_t mb2a = (uint32_t)__cvta_generic_to_shared(&mbar[1]);
    if (tid == 0) { mbar_init(mb1a, 4); mbar_init(mb2a, 4); }
    __syncthreads();
    cluster_sync_();

    if (tid < 128) {
        // ============================ GROUP A ============================
        // W1 rows r0,r1, k-half kh -> registers (2 x 32 u64)
        u64 w1a[32], w1b[32];
        {
            const int g0 = (r0 >> 5) * 128 + rank * 32 + (r0 & 31);
            const int g1 = (r1 >> 5) * 128 + rank * 32 + (r1 & 31);
            const float* s0 = Whh1 + (size_t)g0 * 128 + kh * 64;
            const float* s1 = Whh1 + (size_t)g1 * 128 + kh * 64;
            #pragma unroll
            for (int k = 0; k < 16; k++) {
                ulonglong2 v0 = ((const ulonglong2*)s0)[k];
                ulonglong2 v1 = ((const ulonglong2*)s1)[k];
                w1a[2 * k] = v0.x; w1a[2 * k + 1] = v0.y;
                w1b[2 * k] = v1.x; w1b[2 * k + 1] = v1.y;
            }
        }
        float c1s = 0.f;
        for (int i = 0; i < TSEQ; i++) {
            const int p  = i & 1;
            const int pn = p ^ 1;
            if (i > 0) mbar_wait(mb1a, (uint32_t)((i - 1) & 1));

            float xv = xs[cb][i];   // hoisted: latency hidden under mv1

            // mv1: rows r0,r1 (half kh) . h1(i-1), 4 batches
            {
                const ulonglong2* hA = (const ulonglong2*)(&h1bc[p][0 * ASTRIDE + kh * 68]);
                const ulonglong2* hB = (const ulonglong2*)(&h1bc[p][1 * ASTRIDE + kh * 68]);
                const ulonglong2* hC = (const ulonglong2*)(&h1bc[p][2 * ASTRIDE + kh * 68]);
                const ulonglong2* hD = (const ulonglong2*)(&h1bc[p][3 * ASTRIDE + kh * 68]);
                u64 q00 = 0, q01 = 0, q02 = 0, q03 = 0;
                u64 q10 = 0, q11 = 0, q12 = 0, q13 = 0;
                #pragma unroll
                for (int k = 0; k < 16; k++) {
                    ulonglong2 v0 = hA[k], v1 = hB[k], v2 = hC[k], v3 = hD[k];
                    u64 wa0 = w1a[2 * k], wa1 = w1a[2 * k + 1];
                    q00 = ffma2(wa0, v0.x, q00); q00 = ffma2(wa1, v0.y, q00);
                    q01 = ffma2(wa0, v1.x, q01); q01 = ffma2(wa1, v1.y, q01);
                    q02 = ffma2(wa0, v2.x, q02); q02 = ffma2(wa1, v2.y, q02);
                    q03 = ffma2(wa0, v3.x, q03); q03 = ffma2(wa1, v3.y, q03);
                    u64 wb0 = w1b[2 * k], wb1 = w1b[2 * k + 1];
                    q10 = ffma2(wb0, v0.x, q10); q10 = ffma2(wb1, v0.y, q10);
                    q11 = ffma2(wb0, v1.x, q11); q11 = ffma2(wb1, v1.y, q11);
                    q12 = ffma2(wb0, v2.x, q12); q12 = ffma2(wb1, v2.y, q12);
                    q13 = ffma2(wb0, v3.x, q13); q13 = ffma2(wb1, v3.y, q13);
                }
                float s00 = sum2(q00), s01 = sum2(q01), s02 = sum2(q02), s03 = sum2(q03);
                float s10 = sum2(q10), s11 = sum2(q11), s12 = sum2(q12), s13 = sum2(q13);
                s00 += __shfl_xor_sync(0xffffffffu, s00, 16);
                s01 += __shfl_xor_sync(0xffffffffu, s01, 16);
                s02 += __shfl_xor_sync(0xffffffffu, s02, 16);
                s03 += __shfl_xor_sync(0xffffffffu, s03, 16);
                s10 += __shfl_xor_sync(0xffffffffu, s10, 16);
                s11 += __shfl_xor_sync(0xffffffffu, s11, 16);
                s12 += __shfl_xor_sync(0xffffffffu, s12, 16);
                s13 += __shfl_xor_sync(0xffffffffu, s13, 16);
                if (kh == 0) {
                    float* q0 = &g1buf[r0 * GSTRIDE];
                    float* q1 = &g1buf[r1 * GSTRIDE];
                    q0[0] = s00; q0[1] = s01; q0[2] = s02; q0[3] = s03;
                    q1[0] = s10; q1[1] = s11; q1[2] = s12; q1[3] = s13;
                }
            }
            asm volatile("bar.sync 1, 128;" ::: "memory");
            if (i > 0) mbar_wait(mb2a, (uint32_t)((i - 1) & 1));

            // cell1 (step i)
            {
                float gi = g1buf[(cu)      * GSTRIDE + cb] + fmaf(wih1s[cu],      xv, bias1s[cu]);
                float gf = g1buf[(32 + cu) * GSTRIDE + cb] + fmaf(wih1s[32 + cu], xv, bias1s[32 + cu]);
                float gg = g1buf[(64 + cu) * GSTRIDE + cb] + fmaf(wih1s[64 + cu], xv, bias1s[64 + cu]);
                float go = g1buf[(96 + cu) * GSTRIDE + cb] + fmaf(wih1s[96 + cu], xv, bias1s[96 + cu]);
                c1s = sigm(gf) * c1s + sigm(gi) * tanh_a(gg);
                float h1n = sigm(go) * tanh_a(c1s);
                #pragma unroll
                for (int r = 0; r < 4; r++) {
                    st_cluster_f32(&h1bc[pn][cb * ASTRIDE + pos], r, h1n);
                    st_cluster_f32(&c1bc[pn][cb * ASTRIDE + pos], r, c1s);
                }
            }
            asm volatile("bar.sync 1, 128;" ::: "memory");
            if (lt < 4) mbar_arrive_rank(mb1a, lt);
        }
    } else {
        // ============================ GROUP B ============================
        // Wih2 rows r0,r1, k-half kh -> registers (2 x 32 u64)
        u64 wia[32], wib[32];
        {
            const int g0 = (r0 >> 5) * 128 + rank * 32 + (r0 & 31);
            const int g1 = (r1 >> 5) * 128 + rank * 32 + (r1 & 31);
            const float* s0 = Wih2 + (size_t)g0 * 128 + kh * 64;
            const float* s1 = Wih2 + (size_t)g1 * 128 + kh * 64;
            #pragma unroll
            for (int k = 0; k < 16; k++) {
                ulonglong2 v0 = ((const ulonglong2*)s0)[k];
                ulonglong2 v1 = ((const ulonglong2*)s1)[k];
                wia[2 * k] = v0.x; wia[2 * k + 1] = v0.y;
                wib[2 * k] = v1.x; wib[2 * k + 1] = v1.y;
            }
        }
        float c2s = 0.f;
        float* gh2p = g_h2 + (size_t)(bg0 + cb) * HDIM + slot;

        if (lt < 4) mbar_arrive_rank(mb2a, lt);   // iteration-0 arrive
        for (int i = 1; i <= TSEQ; i++) {
            const int p  = i & 1;
            const int pn = p ^ 1;
            const uint32_t wpar = (uint32_t)((i - 1) & 1);
            mbar_wait(mb1a, wpar);
            mbar_wait(mb2a, wpar);

            // mv2: gates2(step i-1) rows r0,r1 = Wih2(regs).c1 + Whh2(SMEM).h2, kh half
            {
                const ulonglong2* wh0 = (const ulonglong2*)(sW2 + r0 * WSTRIDE + kh * 68);
                const ulonglong2* wh1 = (const ulonglong2*)(sW2 + r1 * WSTRIDE + kh * 68);
                const ulonglong2* cA = (const ulonglong2*)(&c1bc[p][0 * ASTRIDE + kh * 68]);
                const ulonglong2* cB = (const ulonglong2*)(&c1bc[p][1 * ASTRIDE + kh * 68]);
                const ulonglong2* cC = (const ulonglong2*)(&c1bc[p][2 * ASTRIDE + kh * 68]);
                const ulonglong2* cD = (const ulonglong2*)(&c1bc[p][3 * ASTRIDE + kh * 68]);
                const ulonglong2* hA = (const ulonglong2*)(&h2bc[p][0 * ASTRIDE + kh * 68]);
                const ulonglong2* hB = (const ulonglong2*)(&h2bc[p][1 * ASTRIDE + kh * 68]);
                const ulonglong2* hC = (const ulonglong2*)(&h2bc[p][2 * ASTRIDE + kh * 68]);
                const ulonglong2* hD = (const ulonglong2*)(&h2bc[p][3 * ASTRIDE + kh * 68]);
                u64 p00 = 0, p01 = 0, p02 = 0, p03 = 0;
                u64 p10 = 0, p11 = 0, p12 = 0, p13 = 0;
                #pragma unroll
                for (int k = 0; k < 16; k++) {
                    ulonglong2 whA = wh0[k], whB = wh1[k];
                    ulonglong2 v0 = cA[k], v1 = cB[k], v2 = cC[k], v3 = cD[k];
                    ulonglong2 u0 = hA[k], u1 = hB[k], u2 = hC[k], u3 = hD[k];
                    u64 wa0 = wia[2 * k], wa1 = wia[2 * k + 1];
                    u64 wb0 = wib[2 * k], wb1 = wib[2 * k + 1];
                    p00 = ffma2(wa0, v0.x, p00); p00 = ffma2(wa1, v0.y, p00);
                    p00 = ffma2(whA.x, u0.x, p00); p00 = ffma2(whA.y, u0.y, p00);
                    p01 = ffma2(wa0, v1.x, p01); p01 = ffma2(wa1, v1.y, p01);
                    p01 = ffma2(whA.x, u1.x, p01); p01 = ffma2(whA.y, u1.y, p01);
                    p02 = ffma2(wa0, v2.x, p02); p02 = ffma2(wa1, v2.y, p02);
                    p02 = ffma2(whA.x, u2.x, p02); p02 = ffma2(whA.y, u2.y, p02);
                    p03 = ffma2(wa0, v3.x, p03); p03 = ffma2(wa1, v3.y, p03);
                    p03 = ffma2(whA.x, u3.x, p03); p03 = ffma2(whA.y, u3.y, p03);
                    p10 = ffma2(wb0, v0.x, p10); p10 = ffma2(wb1, v0.y, p10);
                    p10 = ffma2(whB.x, u0.x, p10); p10 = ffma2(whB.y, u0.y, p10);
                    p11 = ffma2(wb0, v1.x, p11); p11 = ffma2(wb1, v1.y, p11);
                    p11 = ffma2(whB.x, u1.x, p11); p11 = ffma2(whB.y, u1.y, p11);
                    p12 = ffma2(wb0, v2.x, p12); p12 = ffma2(wb1, v2.y, p12);
                    p12 = ffma2(whB.x, u2.x, p12); p12 = ffma2(whB.y, u2.y, p12);
                    p13 = ffma2(wb0, v3.x, p13); p13 = ffma2(wb1, v3.y, p13);
                    p13 = ffma2(whB.x, u3.x, p13); p13 = ffma2(whB.y, u3.y, p13);
                }
                float s00 = sum2(p00), s01 = sum2(p01), s02 = sum2(p02), s03 = sum2(p03);
                float s10 = sum2(p10), s11 = sum2(p11), s12 = sum2(p12), s13 = sum2(p13);
                s00 += __shfl_xor_sync(0xffffffffu, s00, 16);
                s01 += __shfl_xor_sync(0xffffffffu, s01, 16);
                s02 += __shfl_xor_sync(0xffffffffu, s02, 16);
                s03 += __shfl_xor_sync(0xffffffffu, s03, 16);
                s10 += __shfl_xor_sync(0xffffffffu, s10, 16);
                s11 += __shfl_xor_sync(0xffffffffu, s11, 16);
                s12 += __shfl_xor_sync(0xffffffffu, s12, 16);
                s13 += __shfl_xor_sync(0xffffffffu, s13, 16);
                if (kh == 0) {
                    float* q0 = &g2buf[r0 * GSTRIDE];
                    float* q1 = &g2buf[r1 * GSTRIDE];
                    q0[0] = s00; q0[1] = s01; q0[2] = s02; q0[3] = s03;
                    q1[0] = s10; q1[1] = s11; q1[2] = s12; q1[3] = s13;
                }
            }
            asm volatile("bar.sync 2, 128;" ::: "memory");

            // cell2 (step i-1)
            {
                float gi = g2buf[(cu)      * GSTRIDE + cb] + bias2s[cu];
                float gf = g2buf[(32 + cu) * GSTRIDE + cb] + bias2s[32 + cu];
                float gg = g2buf[(64 + cu) * GSTRIDE + cb] + bias2s[64 + cu];
                float go = g2buf[(96 + cu) * GSTRIDE + cb] + bias2s[96 + cu];
                c2s = sigm(gf) * c2s + sigm(gi) * tanh_a(gg);
                float h2n = sigm(go) * tanh_a(c2s);
                if (i < TSEQ) {
                    #pragma unroll
                    for (int r = 0; r < 4; r++)
                        st_cluster_f32(&h2bc[pn][cb * ASTRIDE + pos], r, h2n);
                }
                gh2p[(size_t)(i - 1) * (BATCH * HDIM)] = h2n;
            }
            asm volatile("bar.sync 2, 128;" ::: "memory");
            if (lt < 4 && i < TSEQ) mbar_arrive_rank(mb2a, lt);
        }
    }
}

// ---------------------------------------------------------------------------
__global__ void dots_kernel(const float* __restrict__ w_t)
{
    int gid  = blockIdx.x * blockDim.x + threadIdx.x;
    int gw   = gid >> 5;
    int lane = gid & 31;
    if (gw >= TSEQ * BATCH) return;
    float4 h = *(const float4*)(g_h2 + (size_t)gw * HDIM + lane * 4);
    float4 a = *(const float4*)(w_t + lane * 4);
    float4 o = *(const float4*)(w_t + HDIM + lane * 4);
    float dh   = h.x * a.x + h.y * a.y + h.z * a.z + h.w * a.w;
    float dold = h.x * o.x + h.y * o.y + h.z * o.z + h.w * o.w;
    #pragma unroll
    for (int off = 16; off; off >>= 1) {
        dh   += __shfl_down_sync(0xffffffffu, dh, off);
        dold += __shfl_down_sync(0xffffffffu, dold, off);
    }
    if (lane == 0) { g_dh[gw] = dh; g_dold[gw] = dold; }
}

// ---------------------------------------------------------------------------
__global__ void __launch_bounds__(256, 1)
attn_fc_kernel(const float* __restrict__ fcW, const float* __restrict__ fcb,
               float* __restrict__ out)
{
    extern __shared__ float sm[];
    float* sFcT = sm;                       // [128][132]
    float* sPre = sFcT + 128 * RSTRIDE;     // [128][132]
    float* sE   = sPre + 128 * RSTRIDE;     // [33][128]
    float* sHd  = sE + 33 * 128;            // [128]
    float* sFcb = sHd + 128;                // [128]
    float* sRed = sFcb + 128;               // [256]

    const int t    = blockIdx.x;
    const int tid  = threadIdx.x;
    const int lane = tid & 31;
    const int warp = tid >> 5;

    for (int idx = tid; idx < 128 * 128; idx += 256) {
        int c = idx >> 7, h = idx & 127;
        sFcT[h * RSTRIDE + c] = fcW[idx];
    }
    if (tid < 128) {
        sFcb[tid] = fcb[tid];
        sHd[tid]  = g_dh[t * BATCH + tid];
    }
    __syncthreads();

    const int s_min = (t < 32) ? (32 - t) : 0;
    const int nsc   = (33 - s_min) * 128;
    float lmax = -1e30f;
    for (int n = tid; n < nsc; n += 256) {
        int s = s_min + (n >> 7), b = n & 127;
        int idx = t - 33 + s;
        float sc = sHd[b] + (idx >= 0 ? g_dold[idx * BATCH + b] : 0.f);
        sE[s * 128 + b] = sc;
        lmax = fmaxf(lmax, sc);
    }
    sRed[tid] = lmax; __syncthreads();
    for (int off = 128; off; off >>= 1) {
        if (tid < off) sRed[tid] = fmaxf(sRed[tid], sRed[tid + off]);
        __syncthreads();
    }
    float mx = sRed[0];
    __syncthreads();
    float lsum = 0.f;
    for (int n = tid; n < nsc; n += 256) {
        int s = s_min + (n >> 7), b = n & 127;
        float e = __expf(sE[s * 128 + b] - mx);
        sE[s * 128 + b] = e;
        lsum += e;
    }
    sRed[tid] = lsum; __syncthreads();
    for (int off = 128; off; off >>= 1) {
        if (tid < off) sRed[tid] += sRed[tid + off];
        __syncthreads();
    }
    float inv = __fdividef(1.f, sRed[0]);
    __syncthreads();

    const int s_att = (t < 33) ? (33 - t) : 0;
    for (int b = warp; b < 128; b += 8) {
        float4 acc; acc.x = acc.y = acc.z = acc.w = 0.f;
        for (int s = s_att; s < 33; s++) {
            float w  = sE[s * 128 + b];
            float4 v = *(const float4*)(g_h2 + (size_t)(t - 33 + s) * (BATCH * HDIM)
                                              + (size_t)b * HDIM + lane * 4);
            acc.x += w * v.x; acc.y += w * v.y; acc.z += w * v.z; acc.w += w * v.w;
        }
        float4 hc = *(const float4*)(g_h2 + (size_t)t * (BATCH * HDIM)
                                           + (size_t)b * HDIM + lane * 4);
        float4 pre;
        pre.x = hc.x + inv * acc.x; pre.y = hc.y + inv * acc.y;
        pre.z = hc.z + inv * acc.z; pre.w = hc.w + inv * acc.w;
        *(float4*)(sPre + b * RSTRIDE + lane * 4) = pre;
    }
    __syncthreads();

    const int c0 = lane * 4;
    float4 bias = *(const float4*)(sFcb + c0);
    for (int r = 0; r < 4; r++) {
        int b0 = (warp + 8 * r) * 4;
        float4 a0, a1, a2, a3;
        a0.x=a0.y=a0.z=a0.w=0.f; a1=a0; a2=a0; a3=a0;
        const float4* p0 = (const float4*)(sPre + (size_t)(b0 + 0) * RSTRIDE);
        const float4* p1 = (const float4*)(sPre + (size_t)(b0 + 1) * RSTRIDE);
        const float4* p2 = (const float4*)(sPre + (size_t)(b0 + 2) * RSTRIDE);
        const float4* p3 = (const float4*)(sPre + (size_t)(b0 + 3) * RSTRIDE);
        #pragma unroll
        for (int h4 = 0; h4 < 32; h4++) {
            float4 q0 = p0[h4], q1 = p1[h4], q2 = p2[h4], q3 = p3[h4];
            #pragma unroll
            for (int hh = 0; hh < 4; hh++) {
                float4 w = *(const float4*)(sFcT + (h4 * 4 + hh) * RSTRIDE + c0);
                float v0 = (&q0.x)[hh], v1 = (&q1.x)[hh], v2 = (&q2.x)[hh], v3 = (&q3.x)[hh];
                a0.x += v0 * w.x; a0.y += v0 * w.y; a0.z += v0 * w.z; a0.w += v0 * w.w;
                a1.x += v1 * w.x; a1.y += v1 * w.y; a1.z += v1 * w.z; a1.w += v1 * w.w;
                a2.x += v2 * w.x; a2.y += v2 * w.y; a2.z += v2 * w.z; a2.w += v2 * w.w;
                a3.x += v3 * w.x; a3.y += v3 * w.y; a3.z += v3 * w.z; a3.w += v3 * w.w;
            }
        }
        a0.x += bias.x; a0.y += bias.y; a0.z += bias.z; a0.w += bias.w;
        a1.x += bias.x; a1.y += bias.y; a1.z += bias.z; a1.w += bias.w;
        a2.x += bias.x; a2.y += bias.y; a2.z += bias.z; a2.w += bias.w;
        a3.x += bias.x; a3.y += bias.y; a3.z += bias.z; a3.w += bias.w;
        size_t obase = (size_t)t * 128 + c0;
        *(float4*)(out + (size_t)(b0 + 0) * (TSEQ * 128) + obase) = a0;
        *(float4*)(out + (size_t)(b0 + 1) * (TSEQ * 128) + obase) = a1;
        *(float4*)(out + (size_t)(b0 + 2) * (TSEQ * 128) + obase) = a2;
        *(float4*)(out + (size_t)(b0 + 3) * (TSEQ * 128) + obase) = a3;
    }
}

// ---------------------------------------------------------------------------
extern "C" void kernel_launch(void* const* d_in, const int* in_sizes, int n_in,
                              void* d_out, int out_size)
{
    const float* x    = (const float*)d_in[0];
    const float* Wih1 = (const float*)d_in[1];
    const float* Whh1 = (const float*)d_in[2];
    const float* bih1 = (const float*)d_in[3];
    const float* bhh1 = (const float*)d_in[4];
    const float* Wih2 = (const float*)d_in[5];
    const float* Whh2 = (const float*)d_in[6];
    const float* bih2 = (const float*)d_in[7];
    const float* bhh2 = (const float*)d_in[8];
    const float* w_t  = (const float*)d_in[9];
    const float* fcW  = (const float*)d_in[10];
    const float* fcb  = (const float*)d_in[11];
    float* out = (float*)d_out;

    const int smem1 = 128 * WSTRIDE * (int)sizeof(float);   // 67584
    const int smem3 = (2 * 128 * RSTRIDE + 33 * 128 + 128 + 128 + 256) * (int)sizeof(float);

    cudaFuncSetAttribute(lstm_seq_kernel, cudaFuncAttributeMaxDynamicSharedMemorySize, smem1);
    cudaFuncSetAttribute(attn_fc_kernel,  cudaFuncAttributeMaxDynamicSharedMemorySize, smem3);

    lstm_seq_kernel<<<128, 256, smem1>>>(x, Wih1, Whh1, bih1, bhh1,
                                         Wih2, Whh2, bih2, bhh2);
    dots_kernel<<<(TSEQ * BATCH * 32) / 256, 256>>>(w_t);
    attn_fc_kernel<<<TSEQ, 256, smem3>>>(fcW, fcb, out);
}